// round 15
// baseline (speedup 1.0000x reference)
#include <cuda_runtime.h>
#include <cuda_fp16.h>
#include <cstdint>

// Problem constants (Qwen2: B=2, S=4096, H=3584, NH=28, NKV=4, D=128)
#define BB 2
#define SS 4096
#define HH 3584
#define NH 28
#define NKV 4
#define DD 128
#define M_ (BB * SS)                  // 8192
#define N_ ((NH + 2 * NKV) * DD)      // 4608
#define K_ HH                         // 3584
#define QTOT ((size_t)BB * NH * SS * DD)   // 29360128
#define KTOT ((size_t)BB * NKV * SS * DD)  // 4194304

#if defined(__CUDA_ARCH__) && defined(__CUDA_ARCH_HAS_FEATURE__)
#  if __CUDA_ARCH_HAS_FEATURE__(SM103_ALL)
#    define USE_TC 1
#  endif
#endif
#ifndef USE_TC
#  define USE_TC 0
#endif

// ===== persistent cg2 kernel config (BK=128: two SW128 column blocks) =====
#define P_BK 128                      // K-chunk: 2 x 64-half column blocks
#define P_NKT (K_ / P_BK)             // 28
#define P_NSTAGE 3
#define P_HALF 16384                  // one 128-row x 64-half column block
#define P_A_BYTES 32768               // A half-tile: 2 column blocks
#define P_B_BYTES 32768               // B half-tile: 2 column blocks
#define P_STAGE (P_A_BYTES + P_B_BYTES)                   // 65536
#define P_SMEM_DATA 1024
#define P_SMEM_BYTES (P_SMEM_DATA + P_NSTAGE * P_STAGE)   // 197632
#define NPT ((M_ / 256) * (N_ / 256)) // 576 pair-tiles
#define NPAIRS 74
#define NTILE_N (N_ / 256)            // 18

// ===== backup (round-6 proven, 423us) =====
#define TC_BM 256
#define TC_BN 256
#define TC_BK 64
#define TC_NKT (K_ / TC_BK)
#define TC_NSTAGE 3
#define TC_A_BYTES (TC_BM * 128)
#define TC_STAGE_BYTES (TC_A_BYTES + TC_BN * 128)
#define TC_SMEM_DATA 1024
#define TC_SMEM_BYTES (TC_SMEM_DATA + TC_NSTAGE * TC_STAGE_BYTES)

// ===== fallback (round-1 proven) =====
#define FB_BM 128
#define FB_BN 128
#define FB_BK 32
#define FB_BKP (FB_BK + 8)
#define FB_NKT (K_ / FB_BK)
#define FB_SMEM_BYTES 67584

__device__ __half g_A[(size_t)M_ * K_];
__device__ __half g_Wt[(size_t)N_ * K_];
__device__ int g_probe_sink;

struct alignas(64) TMap { unsigned char data[128]; };

extern "C" __attribute__((weak)) int cuTensorMapEncodeTiled(
    void* tensorMap, int tensorDataType, unsigned tensorRank, void* globalAddress,
    const unsigned long long* globalDim, const unsigned long long* globalStrides,
    const unsigned* boxDim, const unsigned* elementStrides,
    int interleave, int swizzle, int l2Promotion, int oobFill);

typedef int (*EncodeFn)(void*, int, unsigned, void*,
                        const unsigned long long*, const unsigned long long*,
                        const unsigned*, const unsigned*, int, int, int, int);

// ---------------------------------------------------------------------------
__global__ void arch_probe(int v) {
#if USE_TC
    __shared__ int buf[512];
#else
    __shared__ int buf[256];
#endif
    buf[threadIdx.x & 255] = v;
    __syncthreads();
    g_probe_sink = buf[(threadIdx.x + (unsigned)v) & 255];
}

// ---------------------------------------------------------------------------
__global__ void convert_hidden(const float* __restrict__ x, int n4) {
    int i = blockIdx.x * blockDim.x + threadIdx.x;
    if (i >= n4) return;
    float4 v = reinterpret_cast<const float4*>(x)[i];
    __half2 h0 = __floats2half2_rn(v.x, v.y);
    __half2 h1 = __floats2half2_rn(v.z, v.w);
    reinterpret_cast<__half2*>(g_A)[2 * i]     = h0;
    reinterpret_cast<__half2*>(g_A)[2 * i + 1] = h1;
}

// ---------------------------------------------------------------------------
__global__ void convert_weights(const float* __restrict__ Wq,
                                const float* __restrict__ Wk,
                                const float* __restrict__ Wv) {
    __shared__ __half tile[32][33];
    int n0 = blockIdx.x * 32;
    int k0 = blockIdx.y * 32;
    int x = threadIdx.x, y = threadIdx.y;

    const float* src;
    int ncols, c0;
    if (n0 < NH * DD)               { src = Wq; ncols = NH * DD;  c0 = n0; }
    else if (n0 < (NH + NKV) * DD)  { src = Wk; ncols = NKV * DD; c0 = n0 - NH * DD; }
    else                            { src = Wv; ncols = NKV * DD; c0 = n0 - (NH + NKV) * DD; }

#pragma unroll
    for (int i = 0; i < 4; i++) {
        int kl = y + i * 8;
        tile[kl][x] = __float2half_rn(src[(size_t)(k0 + kl) * ncols + c0 + x]);
    }
    __syncthreads();
#pragma unroll
    for (int i = 0; i < 4; i++) {
        int nl = y + i * 8;
        g_Wt[(size_t)(n0 + nl) * K_ + k0 + x] = tile[x][nl];
    }
}

// ---------------------------------------------------------------------------
__device__ __forceinline__ uint32_t smem_u32(const void* p) {
    return (uint32_t)__cvta_generic_to_shared(p);
}
__device__ __forceinline__ void cp_async16(void* smem_dst, const void* gsrc) {
    asm volatile("cp.async.cg.shared.global [%0], [%1], 16;\n"
                 :: "r"(smem_u32(smem_dst)), "l"(gsrc));
}

extern __shared__ char smem_raw[];

#if USE_TC
__device__ __forceinline__ uint32_t elect_one_pred() {
    uint32_t pred;
    asm volatile("{\n\t.reg .pred p;\n\telect.sync _|p, 0xFFFFFFFF;\n\t"
                 "selp.b32 %0, 1, 0, p;\n\t}" : "=r"(pred));
    return pred;
}
__device__ __forceinline__ uint32_t cluster_rank() {
    uint32_t r;
    asm("mov.u32 %0, %%cluster_ctarank;" : "=r"(r));
    return r;
}
static constexpr uint64_t DESC_BASE_SW128 =
    (uint64_t(2) << 61) | (uint64_t(1) << 46) | (uint64_t(64) << 32) | (uint64_t(1) << 16);
__device__ __forceinline__ uint64_t make_desc(uint32_t addr) {
    return DESC_BASE_SW128 | ((uint64_t)(addr >> 4) & 0x3FFF);
}
static constexpr uint32_t MMA_IDESC_N128 = (1u << 4) | (16u << 17) | (8u << 24);
// cg2: f16 x f16 -> f32, M=256 (16<<24), N=256 (32<<17)
static constexpr uint32_t MMA_IDESC_CG2  = (1u << 4) | (32u << 17) | (16u << 24);

__device__ __forceinline__ void mma_f16_ss(uint32_t d_tmem, uint64_t a_desc,
                                           uint64_t b_desc, uint32_t idesc,
                                           uint32_t en) {
    asm volatile(
        "{\n\t.reg .pred p;\n\tsetp.ne.u32 p, %5, 0;\n\t"
        "tcgen05.mma.cta_group::1.kind::f16 [%0], %1, %2, %3, {%4, %4, %4, %4}, p;\n\t}"
        :: "r"(d_tmem), "l"(a_desc), "l"(b_desc), "r"(idesc), "r"(0u), "r"(en)
        : "memory");
}
__device__ __forceinline__ void mma_f16_ss_cg2(uint32_t d_tmem, uint64_t a_desc,
                                               uint64_t b_desc, uint32_t en) {
    asm volatile(
        "{\n\t.reg .pred p;\n\tsetp.ne.u32 p, %5, 0;\n\t"
        "tcgen05.mma.cta_group::2.kind::f16 [%0], %1, %2, %3, "
        "{%4, %4, %4, %4, %4, %4, %4, %4}, p;\n\t}"
        :: "r"(d_tmem), "l"(a_desc), "l"(b_desc), "r"(MMA_IDESC_CG2), "r"(0u), "r"(en)
        : "memory");
}
#define TC_ALLOC(smem_addr, ncols) \
    asm volatile("tcgen05.alloc.cta_group::1.sync.aligned.shared::cta.b32 [%0], %1;" \
                 :: "r"(smem_addr), "r"(ncols) : "memory")
#define TC_DEALLOC(tmem, ncols) \
    asm volatile("tcgen05.dealloc.cta_group::1.sync.aligned.b32 %0, %1;" :: "r"(tmem), "r"(ncols))
#define TC_RELINQ() \
    asm volatile("tcgen05.relinquish_alloc_permit.cta_group::1.sync.aligned;")
#define TC_ALLOC_CG2(smem_addr, ncols) \
    asm volatile("tcgen05.alloc.cta_group::2.sync.aligned.shared::cta.b32 [%0], %1;" \
                 :: "r"(smem_addr), "r"(ncols) : "memory")
#define TC_DEALLOC_CG2(tmem, ncols) \
    asm volatile("tcgen05.dealloc.cta_group::2.sync.aligned.b32 %0, %1;" :: "r"(tmem), "r"(ncols))
#define TC_RELINQ_CG2() \
    asm volatile("tcgen05.relinquish_alloc_permit.cta_group::2.sync.aligned;")
#define TC_COMMIT(mbar) \
    asm volatile("tcgen05.commit.cta_group::1.mbarrier::arrive::one.shared::cluster.b64 [%0];" \
                 :: "r"(mbar) : "memory")
#define TC_COMMIT_MC_CG2(mbar, mask) \
    asm volatile("tcgen05.commit.cta_group::2.mbarrier::arrive::one.shared::cluster.multicast::cluster.b64 [%0], %1;" \
                 :: "r"(mbar), "h"((uint16_t)(mask)) : "memory")
#define TC_FENCE_AFTER()  asm volatile("tcgen05.fence::after_thread_sync;" ::: "memory")
#define TC_WAIT_LD() asm volatile("tcgen05.wait::ld.sync.aligned;" ::: "memory")
#define MBAR_INIT(mbar, cnt) \
    asm volatile("mbarrier.init.shared.b64 [%0], %1;" :: "r"(mbar), "r"(cnt) : "memory")
#define MBAR_EXPECT_TX(mbar, bytes) \
    asm volatile("mbarrier.arrive.expect_tx.shared.b64 _, [%0], %1;" \
                 :: "r"(mbar), "r"(bytes) : "memory")
#define MBAR_ARRIVE(mbar) \
    asm volatile("mbarrier.arrive.shared.b64 _, [%0];" :: "r"(mbar) : "memory")
#define MBAR_ARRIVE_CLUSTER(local_mbar, target_rank) \
    asm volatile( \
        "{\n\t.reg .b32 remAddr;\n\t" \
        "mapa.shared::cluster.u32 remAddr, %0, %1;\n\t" \
        "mbarrier.arrive.shared::cluster.b64 _, [remAddr];\n\t}" \
        :: "r"(local_mbar), "r"(target_rank) : "memory")
#define FENCE_ASYNC_SHARED() asm volatile("fence.proxy.async.shared::cta;" ::: "memory")
#define CLUSTER_SYNC() do { \
    asm volatile("barrier.cluster.arrive.aligned;" ::: "memory"); \
    asm volatile("barrier.cluster.wait.aligned;" ::: "memory"); \
} while (0)

// cg2 TMA: dest local SMEM, complete_tx to LEADER's barrier (bit 24 cleared).
__device__ __forceinline__ void tma_load_3d_cg2(uint32_t smem_addr, const void* tmap,
                                                int cx, int cy, uint32_t mbar) {
    asm volatile(
        "{\n\t.reg .b32 lb;\n\t"
        "and.b32 lb, %4, 0xFEFFFFFF;\n\t"
        "cp.async.bulk.tensor.3d.cta_group::2.shared::cluster.global"
        ".tile.mbarrier::complete_tx::bytes [%0], [%1, {%2, %3, 0}], [lb];\n\t}"
        :: "r"(smem_addr), "l"(tmap), "r"(cx), "r"(cy), "r"(mbar) : "memory");
}

#define LDTM_X32(r, addr) \
    asm volatile( \
        "tcgen05.ld.sync.aligned.32x32b.x32.b32 " \
        "{%0, %1, %2, %3, %4, %5, %6, %7, " \
        " %8, %9, %10, %11, %12, %13, %14, %15, " \
        " %16, %17, %18, %19, %20, %21, %22, %23, " \
        " %24, %25, %26, %27, %28, %29, %30, %31}, [%32];" \
        : "=r"((r)[0]),  "=r"((r)[1]),  "=r"((r)[2]),  "=r"((r)[3]), \
          "=r"((r)[4]),  "=r"((r)[5]),  "=r"((r)[6]),  "=r"((r)[7]), \
          "=r"((r)[8]),  "=r"((r)[9]),  "=r"((r)[10]), "=r"((r)[11]), \
          "=r"((r)[12]), "=r"((r)[13]), "=r"((r)[14]), "=r"((r)[15]), \
          "=r"((r)[16]), "=r"((r)[17]), "=r"((r)[18]), "=r"((r)[19]), \
          "=r"((r)[20]), "=r"((r)[21]), "=r"((r)[22]), "=r"((r)[23]), \
          "=r"((r)[24]), "=r"((r)[25]), "=r"((r)[26]), "=r"((r)[27]), \
          "=r"((r)[28]), "=r"((r)[29]), "=r"((r)[30]), "=r"((r)[31]) \
        : "r"(addr))

__device__ __forceinline__ void mbar_wait_parity(uint32_t mbar, uint32_t parity) {
    asm volatile(
        "{\n\t.reg .pred P1;\n\t"
        "WAIT_LOOP_%=:\n\t"
        "mbarrier.try_wait.parity.acquire.cta.shared::cta.b64 P1, [%0], %1, 0x989680;\n\t"
        "@P1 bra.uni WAIT_DONE_%=;\n\t"
        "bra.uni WAIT_LOOP_%=;\n\t"
        "WAIT_DONE_%=:\n\t}"
        :: "r"(mbar), "r"(parity) : "memory");
}

// Epilogue for a local BM=128 x BN=256 half-tile (round-12 proven mapping).
__device__ __forceinline__ void p_epilogue(
    uint32_t dtmem, int wid, int lane, int m0, int n0,
    const float* cosb, const float* sinb,
    const float* bq, const float* bk, const float* bv, float* out) {
    const int row = ((wid & 3) << 5) + lane;
    const int m = m0 + row;
    const int bt = m >> 12;
    const int s  = m & 4095;
    const int nbase = n0 + (wid >> 2) * 128;
    const int head = nbase >> 7;
    const bool isq = head < NH;
    const bool isk = (head >= NH) && (head < NH + NKV);
    const float* bias;
    size_t obase;
    if (isq)      { bias = bq + nbase;
                    obase = (((size_t)bt * NH + head) * SS + s) * DD; }
    else if (isk) { bias = bk + (nbase - NH * DD);
                    obase = QTOT + (((size_t)bt * NKV + (head - NH)) * SS + s) * DD; }
    else          { bias = bv + (nbase - (NH + NKV) * DD);
                    obase = QTOT + KTOT + (((size_t)bt * NKV + (head - NH - NKV)) * SS + s) * DD; }
    const uint32_t dbase = dtmem + (wid >> 2) * 128;

#pragma unroll
    for (int half = 0; half < 2; half++) {
        uint32_t rlo[32], rhi[32];
        LDTM_X32(rlo, dbase + half * 32);
        LDTM_X32(rhi, dbase + half * 32 + 64);
        TC_WAIT_LD();

        float vlo[32], vhi[32];
#pragma unroll
        for (int i = 0; i < 32; i++) {
            vlo[i] = __uint_as_float(rlo[i]) + bias[half * 32 + i];
            vhi[i] = __uint_as_float(rhi[i]) + bias[half * 32 + 64 + i];
        }
        if (isq || isk) {
            const float* cp = cosb + (size_t)m * DD + half * 32;
            const float* sp = sinb + (size_t)m * DD + half * 32;
#pragma unroll
            for (int i = 0; i < 32; i++) {
                float c = cp[i], sn = sp[i];
                float lo = vlo[i] * c - vhi[i] * sn;
                float hi = vhi[i] * c + vlo[i] * sn;
                vlo[i] = lo; vhi[i] = hi;
            }
        }
        float* o = out + obase + half * 32;
#pragma unroll
        for (int i = 0; i < 8; i++) {
            *reinterpret_cast<float4*>(o + i * 4) =
                make_float4(vlo[i*4], vlo[i*4+1], vlo[i*4+2], vlo[i*4+3]);
            *reinterpret_cast<float4*>(o + 64 + i * 4) =
                make_float4(vhi[i*4], vhi[i*4+1], vhi[i*4+2], vhi[i*4+3]);
        }
    }
}

// Big-tile epilogue for the backup kernel (round-6 proven).
__device__ __forceinline__ void tc_epilogue(
    uint32_t tmem_base, int wid, int lane, int m0, int n0,
    const float* cosb, const float* sinb,
    const float* bq, const float* bk, const float* bv, float* out) {
    const int sub = wid >> 2;
    const int row = ((wid & 3) << 5) + lane;
    const int m = m0 + sub * 128 + row;
    const int bt = m >> 12;
    const int s  = m & 4095;
    const uint32_t dbase = tmem_base + sub * 256;

#pragma unroll
    for (int hc = 0; hc < 2; hc++) {
        const int nbase = n0 + hc * 128;
        const int head = nbase >> 7;
        const bool isq = head < NH;
        const bool isk = (head >= NH) && (head < NH + NKV);
        const float* bias;
        size_t obase;
        if (isq)      { bias = bq + nbase;
                        obase = (((size_t)bt * NH + head) * SS + s) * DD; }
        else if (isk) { bias = bk + (nbase - NH * DD);
                        obase = QTOT + (((size_t)bt * NKV + (head - NH)) * SS + s) * DD; }
        else          { bias = bv + (nbase - (NH + NKV) * DD);
                        obase = QTOT + KTOT + (((size_t)bt * NKV + (head - NH - NKV)) * SS + s) * DD; }

#pragma unroll
        for (int half = 0; half < 2; half++) {
            uint32_t rlo[32], rhi[32];
            LDTM_X32(rlo, dbase + hc * 128 + half * 32);
            LDTM_X32(rhi, dbase + hc * 128 + half * 32 + 64);
            TC_WAIT_LD();

            float vlo[32], vhi[32];
#pragma unroll
            for (int i = 0; i < 32; i++) {
                vlo[i] = __uint_as_float(rlo[i]) + bias[half * 32 + i];
                vhi[i] = __uint_as_float(rhi[i]) + bias[half * 32 + 64 + i];
            }
            if (isq || isk) {
                const float* cp = cosb + (size_t)m * DD + half * 32;
                const float* sp = sinb + (size_t)m * DD + half * 32;
#pragma unroll
                for (int i = 0; i < 32; i++) {
                    float c = cp[i], sn = sp[i];
                    float lo = vlo[i] * c - vhi[i] * sn;
                    float hi = vhi[i] * c + vlo[i] * sn;
                    vlo[i] = lo; vhi[i] = hi;
                }
            }
            float* o = out + obase + half * 32;
#pragma unroll
            for (int i = 0; i < 8; i++) {
                *reinterpret_cast<float4*>(o + i * 4) =
                    make_float4(vlo[i*4], vlo[i*4+1], vlo[i*4+2], vlo[i*4+3]);
                *reinterpret_cast<float4*>(o + 64 + i * 4) =
                    make_float4(vhi[i*4], vhi[i*4+1], vhi[i*4+2], vhi[i*4+3]);
            }
        }
    }
}
#endif  // USE_TC

// ===========================================================================
// PRIMARY: persistent cluster(2,1,1) cta_group::2 tcgen05 kernel, BK=128.
// grid (2, 74) = 148 persistent CTAs, pair = blockIdx.y, rank along x.
// Pair tile = M256 x N256. Each CTA: A-half + B-half, each 2 column blocks.
// Per iteration: 4 TMA loads, 8 cg2 dispatches, ONE barrier cycle (64KB).
// Leader's FULL bar expect_tx = 128KB (both CTAs' 64KB).
// TMEM halves 0/256 double-buffered: epilogue(t) overlaps mainloop(t+1).
// Warps 0-7: epilogue. Warp 8 lane0: producer. Warp 9 lane0 (leader): MMA.
// ===========================================================================
__global__ __launch_bounds__(320, 1) __cluster_dims__(2, 1, 1)
void qkv_gemm_tma(const __grid_constant__ TMap tma_a,
                  const __grid_constant__ TMap tma_b,
                  const float* __restrict__ cosb, const float* __restrict__ sinb,
                  const float* __restrict__ bq, const float* __restrict__ bk,
                  const float* __restrict__ bv, float* __restrict__ out) {
#if USE_TC
    const int tid  = threadIdx.x;
    const int wid  = tid >> 5, lane = tid & 31;
    const uint32_t rank = cluster_rank();      // 0/1 along x
    const int pair = blockIdx.y;

    const uint32_t smem_base = smem_u32(smem_raw);
    const uint32_t FULL0 = smem_base + 16, EMPTY0 = smem_base + 24;
    const uint32_t MDONE0 = smem_base + 80, EDONE0 = smem_base + 96;

    if (wid == 0) TC_ALLOC_CG2(smem_base, 512);
    if (tid == 0) {
#pragma unroll
        for (int s = 0; s < P_NSTAGE; s++) {
            MBAR_INIT(FULL0 + s * 16, 1);     // leader: expect_tx arrival
            MBAR_INIT(EMPTY0 + s * 16, 1);    // one cg2 commit-mc arrival
        }
        MBAR_INIT(MDONE0, 1);     MBAR_INIT(MDONE0 + 8, 1);
        MBAR_INIT(EDONE0, 16);    MBAR_INIT(EDONE0 + 8, 16);  // 8 warps x 2 CTAs
    }
    __syncthreads();
    CLUSTER_SYNC();

    uint32_t tmem_base;
    asm volatile("ld.shared.b32 %0, [%1];" : "=r"(tmem_base) : "r"(smem_base));

    if (tid == 256) {
        // ================= TMA producer (both CTAs) =================
        uint32_t pph = 1;
        int slot = 0;
        for (int pt = pair; pt < NPT; pt += NPAIRS) {
            const int m0 = (pt / NTILE_N) * 256 + (int)rank * 128;  // my A half
            const int n0 = (pt % NTILE_N) * 256 + (int)rank * 128;  // my B half
            for (int kt = 0; kt < P_NKT; kt++) {
                mbar_wait_parity(EMPTY0 + slot * 16, pph);
                uint32_t sa = smem_base + P_SMEM_DATA + slot * P_STAGE;
                uint32_t fb = FULL0 + slot * 16;
                if (rank == 0)
                    MBAR_EXPECT_TX(fb, 2 * P_STAGE);   // 128KB across both CTAs
                int kc = kt * P_BK;
                tma_load_3d_cg2(sa,                        &tma_a, kc,      m0, fb);
                tma_load_3d_cg2(sa + P_HALF,               &tma_a, kc + 64, m0, fb);
                tma_load_3d_cg2(sa + P_A_BYTES,            &tma_b, kc,      n0, fb);
                tma_load_3d_cg2(sa + P_A_BYTES + P_HALF,   &tma_b, kc + 64, n0, fb);
                if (++slot == P_NSTAGE) { slot = 0; pph ^= 1; }
            }
        }
    } else if (tid == 288 && rank == 0) {
        // ================= MMA issuer (leader only) =================
        uint32_t cph = 0;
        int slot = 0;
        uint32_t eph[2] = {1, 1};
        int ti = 0;
        for (int pt = pair; pt < NPT; pt += NPAIRS) {
            const int half = ti & 1;
            mbar_wait_parity(EDONE0 + half * 8, eph[half]);  // both epilogues done
            eph[half] ^= 1;
            const uint32_t dt = tmem_base + half * 256;
            for (int kt = 0; kt < P_NKT; kt++) {
                mbar_wait_parity(FULL0 + slot * 16, cph);
                uint32_t sa = smem_base + P_SMEM_DATA + slot * P_STAGE;
                uint64_t ad0 = make_desc(sa);                      // A cols 0..63
                uint64_t ad1 = make_desc(sa + P_HALF);             // A cols 64..127
                uint64_t bd0 = make_desc(sa + P_A_BYTES);          // B cols 0..63
                uint64_t bd1 = make_desc(sa + P_A_BYTES + P_HALF); // B cols 64..127
#pragma unroll
                for (int ks = 0; ks < 8; ks++) {
                    uint32_t en = (kt > 0 || ks > 0) ? 1u : 0u;
                    uint64_t ad = (ks < 4) ? ad0 : ad1;
                    uint64_t bd = (ks < 4) ? bd0 : bd1;
                    mma_f16_ss_cg2(dt, ad + (ks & 3) * 2, bd + (ks & 3) * 2, en);
                }
                TC_COMMIT_MC_CG2(EMPTY0 + slot * 16, 0x3);
                if (++slot == P_NSTAGE) { slot = 0; cph ^= 1; }
            }
            TC_COMMIT_MC_CG2(MDONE0 + half * 8, 0x3);     // tile done, both CTAs
            ti++;
        }
    } else if (wid < 8) {
        // ================= epilogue warps (both CTAs) =================
        uint32_t mph[2] = {0, 0};
        int ti = 0;
        for (int pt = pair; pt < NPT; pt += NPAIRS) {
            const int half = ti & 1;
            const int m0 = (pt / NTILE_N) * 256 + (int)rank * 128;
            const int n0 = (pt % NTILE_N) * 256;
            mbar_wait_parity(MDONE0 + half * 8, mph[half]);
            mph[half] ^= 1;
            TC_FENCE_AFTER();
            p_epilogue(tmem_base + half * 256, wid, lane, m0, n0,
                       cosb, sinb, bq, bk, bv, out);
            if (lane == 0) MBAR_ARRIVE_CLUSTER(EDONE0 + half * 8, 0u);  // leader's bar
            ti++;
        }
    }

    __syncthreads();
    CLUSTER_SYNC();
    if (wid == 0) {
        TC_RELINQ_CG2();
        TC_DEALLOC_CG2(tmem_base, 512);
    }
    CLUSTER_SYNC();
#endif  // USE_TC
}

// ===========================================================================
// cp.async tcgen05 kernel — ROUND-6 PROVEN (423 us) backup. grid (18, 32).
// ===========================================================================
__global__ __launch_bounds__(256, 1)
void qkv_gemm_tc(const float* __restrict__ cosb, const float* __restrict__ sinb,
                 const float* __restrict__ bq, const float* __restrict__ bk,
                 const float* __restrict__ bv, float* __restrict__ out) {
#if USE_TC
    const int tid  = threadIdx.x;
    const int wid  = tid >> 5, lane = tid & 31;
    const int m0 = blockIdx.y * TC_BM;
    const int n0 = blockIdx.x * TC_BN;

    const uint32_t smem_base = smem_u32(smem_raw);
    const uint32_t mbar = smem_base + 8;

    if (wid == 0) TC_ALLOC(smem_base, 512);
    if (tid == 0) MBAR_INIT(mbar, 1);
    __syncthreads();
    uint32_t tmem_base;
    asm volatile("ld.shared.b32 %0, [%1];" : "=r"(tmem_base) : "r"(smem_base));

    const int lc = tid & 7;
    const int lr = tid >> 3;
    auto load_tile = [&](int buf, int kt) {
        char* sb = smem_raw + TC_SMEM_DATA + buf * TC_STAGE_BYTES;
        const __half* Ag = g_A + (size_t)(m0 + lr) * K_ + kt * TC_BK + lc * 8;
#pragma unroll
        for (int i = 0; i < 8; i++) {
            int row = lr + i * 32;
            uint32_t off = row * 128 + ((lc ^ (row & 7)) * 16);
            cp_async16(sb + off, Ag + (size_t)(i * 32) * K_);
        }
        const __half* Bg = g_Wt + (size_t)(n0 + lr) * K_ + kt * TC_BK + lc * 8;
#pragma unroll
        for (int i = 0; i < 8; i++) {
            int row = lr + i * 32;
            uint32_t off = TC_A_BYTES + row * 128 + ((lc ^ (row & 7)) * 16);
            cp_async16(sb + off, Bg + (size_t)(i * 32) * K_);
        }
    };

    load_tile(0, 0);
    asm volatile("cp.async.commit_group;\n");
    load_tile(1, 1);
    asm volatile("cp.async.commit_group;\n");

    uint32_t ph = 0;
    for (int kt = 0; kt < TC_NKT; kt++) {
        if (kt + 1 < TC_NKT) {
            asm volatile("cp.async.wait_group 1;\n");
        } else {
            asm volatile("cp.async.wait_group 0;\n");
        }
        __syncthreads();

        if (wid == 0) {
            FENCE_ASYNC_SHARED();
            if (elect_one_pred()) {
                uint32_t sa = smem_base + TC_SMEM_DATA + (kt % TC_NSTAGE) * TC_STAGE_BYTES;
                uint64_t ad0 = make_desc(sa);
                uint64_t ad1 = make_desc(sa + 16384);
                uint64_t bd0 = make_desc(sa + TC_A_BYTES);
                uint64_t bd1 = make_desc(sa + TC_A_BYTES + 16384);
#pragma unroll
                for (int ks = 0; ks < 4; ks++) {
                    uint32_t en = (kt > 0 || ks > 0) ? 1u : 0u;
                    mma_f16_ss(tmem_base,       ad0 + ks * 2, bd0 + ks * 2, MMA_IDESC_N128, en);
                    mma_f16_ss(tmem_base + 128, ad0 + ks * 2, bd1 + ks * 2, MMA_IDESC_N128, en);
                    mma_f16_ss(tmem_base + 256, ad1 + ks * 2, bd0 + ks * 2, MMA_IDESC_N128, en);
                    mma_f16_ss(tmem_base + 384, ad1 + ks * 2, bd1 + ks * 2, MMA_IDESC_N128, en);
                }
                TC_COMMIT(mbar);
            }
        }
        if (kt >= 1) { mbar_wait_parity(mbar, ph); ph ^= 1; }

        if (kt + 2 < TC_NKT) {
            load_tile((kt + 2) % TC_NSTAGE, kt + 2);
            asm volatile("cp.async.commit_group;\n");
        }
    }
    mbar_wait_parity(mbar, ph);
    TC_FENCE_AFTER();

    tc_epilogue(tmem_base, wid, lane, m0, n0, cosb, sinb, bq, bk, bv, out);

    __syncthreads();
    if (wid == 0) {
        TC_RELINQ();
        TC_DEALLOC(tmem_base, 512);
    }
#endif  // USE_TC
}

// ===========================================================================
// Fallback kernel — ROUND-1 PROVEN CODE, VERBATIM SEMANTICS.
// ===========================================================================
__device__ __forceinline__ void ldsm_x4(uint32_t& r0, uint32_t& r1, uint32_t& r2,
                                        uint32_t& r3, const void* p) {
    uint32_t a = (uint32_t)__cvta_generic_to_shared(p);
    asm volatile("ldmatrix.sync.aligned.m8n8.x4.shared.b16 {%0,%1,%2,%3}, [%4];\n"
                 : "=r"(r0), "=r"(r1), "=r"(r2), "=r"(r3) : "r"(a));
}
__device__ __forceinline__ void mma16816(float* c, const uint32_t* a, const uint32_t* b) {
    asm volatile(
        "mma.sync.aligned.m16n8k16.row.col.f32.f16.f16.f32 "
        "{%0,%1,%2,%3}, {%4,%5,%6,%7}, {%8,%9}, {%0,%1,%2,%3};\n"
        : "+f"(c[0]), "+f"(c[1]), "+f"(c[2]), "+f"(c[3])
        : "r"(a[0]), "r"(a[1]), "r"(a[2]), "r"(a[3]), "r"(b[0]), "r"(b[1]));
}

__global__ __launch_bounds__(256, 2) void qkv_gemm_fb(
    const float* __restrict__ cosb, const float* __restrict__ sinb,
    const float* __restrict__ bq, const float* __restrict__ bk,
    const float* __restrict__ bv, float* __restrict__ out) {

    __half (*As)[FB_BM][FB_BKP] = reinterpret_cast<__half (*)[FB_BM][FB_BKP]>(smem_raw);
    __half (*Bs)[FB_BN][FB_BKP] =
        reinterpret_cast<__half (*)[FB_BN][FB_BKP]>(smem_raw + 2 * FB_BM * FB_BKP * 2);

    const int tid  = threadIdx.x;
    const int warp = tid >> 5, lane = tid & 31;
    const int wm = warp & 3, wn = warp >> 2;
    const int tileN = blockIdx.x;
    const int m0 = blockIdx.y * FB_BM;
    const int n0 = tileN * FB_BN;

    const int lrow = tid >> 2;
    const int lch  = tid & 3;

    float acc[2][8][4];
#pragma unroll
    for (int i = 0; i < 2; i++)
#pragma unroll
        for (int j = 0; j < 8; j++)
#pragma unroll
            for (int l = 0; l < 4; l++) acc[i][j][l] = 0.f;

    auto load_tile = [&](int buf, int kt) {
        const __half* Ag = g_A + (size_t)(m0 + lrow) * K_ + kt * FB_BK + lch * 8;
        cp_async16(&As[buf][lrow][lch * 8], Ag);
        cp_async16(&As[buf][lrow + 64][lch * 8], Ag + (size_t)64 * K_);
        const __half* Bg = g_Wt + (size_t)(n0 + lrow) * K_ + kt * FB_BK + lch * 8;
        cp_async16(&Bs[buf][lrow][lch * 8], Bg);
        cp_async16(&Bs[buf][lrow + 64][lch * 8], Bg + (size_t)64 * K_);
    };

    load_tile(0, 0);
    asm volatile("cp.async.commit_group;\n");

    for (int kt = 0; kt < FB_NKT; kt++) {
        asm volatile("cp.async.wait_group 0;\n");
        __syncthreads();
        if (kt + 1 < FB_NKT) {
            load_tile((kt + 1) & 1, kt + 1);
            asm volatile("cp.async.commit_group;\n");
        }
        const int buf = kt & 1;

#pragma unroll
        for (int ks = 0; ks < 2; ks++) {
            uint32_t a[2][4];
            uint32_t b[8][2];
            const int kc = ks * 16 + (lane >> 4) * 8;
            const int rsel = lane & 15;
#pragma unroll
            for (int fm = 0; fm < 2; fm++)
                ldsm_x4(a[fm][0], a[fm][1], a[fm][2], a[fm][3],
                        &As[buf][wm * 32 + fm * 16 + rsel][kc]);
#pragma unroll
            for (int g = 0; g < 4; g++) {
                uint32_t t0, t1, t2, t3;
                ldsm_x4(t0, t1, t2, t3, &Bs[buf][wn * 64 + g * 16 + rsel][kc]);
                b[g * 2][0] = t0;     b[g * 2][1] = t2;
                b[g * 2 + 1][0] = t1; b[g * 2 + 1][1] = t3;
            }
#pragma unroll
            for (int fm = 0; fm < 2; fm++)
#pragma unroll
                for (int fn = 0; fn < 8; fn++)
                    mma16816(acc[fm][fn], a[fm], b[fn]);
        }
    }

    __syncthreads();
    float (*Cs)[132] = reinterpret_cast<float (*)[132]>(smem_raw);
#pragma unroll
    for (int fm = 0; fm < 2; fm++) {
        int r = wm * 32 + fm * 16 + (lane >> 2);
#pragma unroll
        for (int fn = 0; fn < 8; fn++) {
            int c = wn * 64 + fn * 8 + (lane & 3) * 2;
            Cs[r][c]         = acc[fm][fn][0];
            Cs[r][c + 1]     = acc[fm][fn][1];
            Cs[r + 8][c]     = acc[fm][fn][2];
            Cs[r + 8][c + 1] = acc[fm][fn][3];
        }
    }
    __syncthreads();

    const bool is_q = (tileN < NH);
    const bool is_k = (tileN >= NH) && (tileN < NH + NKV);
    const float* bias;
    if (is_q)       bias = bq + n0;
    else if (is_k)  bias = bk + (n0 - NH * DD);
    else            bias = bv + (n0 - (NH + NKV) * DD);

#pragma unroll 4
    for (int it = 0; it < 16; it++) {
        int r = (tid >> 5) + it * 8;
        int c = (tid & 31) * 4;
        int m = m0 + r;
        int bt = m >> 12;
        int s  = m & 4095;

        float vv[4];
        if (is_q || is_k) {
#pragma unroll
            for (int j = 0; j < 4; j++) {
                int cj = c + j;
                float val = Cs[r][cj] + bias[cj];
                float pr  = Cs[r][cj ^ 64] + bias[cj ^ 64];
                float cse = cosb[(size_t)m * DD + cj];
                float sne = sinb[(size_t)m * DD + cj];
                float rot = (cj < 64) ? -pr : pr;
                vv[j] = val * cse + rot * sne;
            }
        } else {
#pragma unroll
            for (int j = 0; j < 4; j++) vv[j] = Cs[r][c + j] + bias[c + j];
        }

        size_t off;
        if (is_q)
            off = (((size_t)bt * NH + tileN) * SS + s) * DD + c;
        else if (is_k)
            off = QTOT + (((size_t)bt * NKV + (tileN - NH)) * SS + s) * DD + c;
        else
            off = QTOT + KTOT + (((size_t)bt * NKV + (tileN - NH - NKV)) * SS + s) * DD + c;

        *reinterpret_cast<float4*>(out + off) = make_float4(vv[0], vv[1], vv[2], vv[3]);
    }
}

// ---------------------------------------------------------------------------
extern "C" void kernel_launch(void* const* d_in, const int* in_sizes, int n_in,
                              void* d_out, int out_size) {
    const float* hs   = (const float*)d_in[0];
    const float* cosb = (const float*)d_in[1];
    const float* sinb = (const float*)d_in[2];
    const float* Wq   = (const float*)d_in[3];
    const float* bq   = (const float*)d_in[4];
    const float* Wk   = (const float*)d_in[5];
    const float* bk   = (const float*)d_in[6];
    const float* Wv   = (const float*)d_in[7];
    const float* bv   = (const float*)d_in[8];
    float* out = (float*)d_out;

    cudaFuncAttributes pa;
    bool use_tc = false;
    if (cudaFuncGetAttributes(&pa, arch_probe) == cudaSuccess)
        use_tc = (pa.sharedSizeBytes >= 2048);

    int n4 = (M_ * K_) / 4;
    convert_hidden<<<(n4 + 255) / 256, 256>>>(hs, n4);

    dim3 gw(N_ / 32, K_ / 32);
    convert_weights<<<gw, dim3(32, 8)>>>(Wq, Wk, Wv);

    if (use_tc) {
        EncodeFn enc = nullptr;
        {
            void* p = nullptr;
            cudaDriverEntryPointQueryResult st;
            if (cudaGetDriverEntryPoint("cuTensorMapEncodeTiled", &p,
                                        cudaEnableDefault, &st) == cudaSuccess &&
                st == cudaDriverEntryPointSuccess && p)
                enc = (EncodeFn)p;
        }
        if (!enc && &cuTensorMapEncodeTiled != nullptr)
            enc = (EncodeFn)cuTensorMapEncodeTiled;

        bool tma_ok = false;
        TMap ta, tb;
        if (enc) {
            void* pA = nullptr; void* pB = nullptr;
            cudaGetSymbolAddress(&pA, g_A);
            cudaGetSymbolAddress(&pB, g_Wt);
            if (pA && pB) {
                unsigned long long dimsA[3] = { (unsigned long long)K_, (unsigned long long)M_, 1 };
                unsigned long long dimsB[3] = { (unsigned long long)K_, (unsigned long long)N_, 1 };
                unsigned long long strA[2]  = { (unsigned long long)K_ * 2,
                                                (unsigned long long)K_ * 2 * M_ };
                unsigned long long strB[2]  = { (unsigned long long)K_ * 2,
                                                (unsigned long long)K_ * 2 * N_ };
                unsigned boxH[3] = { 64, 128, 1 };   // 64-half x 128-row column blocks
                unsigned es[3] = { 1, 1, 1 };
                int r1 = enc(&ta, 6, 3, pA, dimsA, strA, boxH, es, 0, 3, 2, 0);
                int r2 = enc(&tb, 6, 3, pB, dimsB, strB, boxH, es, 0, 3, 2, 0);
                tma_ok = (r1 == 0 && r2 == 0);
            }
        }
        if (tma_ok) {
            cudaFuncSetAttribute(qkv_gemm_tma, cudaFuncAttributeMaxDynamicSharedMemorySize,
                                 P_SMEM_BYTES);
            dim3 gg(2, NPAIRS);                // 148 persistent CTAs, cluster (2,1,1)
            qkv_gemm_tma<<<gg, 320, P_SMEM_BYTES>>>(ta, tb, cosb, sinb, bq, bk, bv, out);
        } else {
            cudaFuncSetAttribute(qkv_gemm_tc, cudaFuncAttributeMaxDynamicSharedMemorySize,
                                 TC_SMEM_BYTES);
            dim3 gg(N_ / TC_BN, M_ / TC_BM);
            qkv_gemm_tc<<<gg, 256, TC_SMEM_BYTES>>>(cosb, sinb, bq, bk, bv, out);
        }
    } else {
        cudaFuncSetAttribute(qkv_gemm_fb, cudaFuncAttributeMaxDynamicSharedMemorySize,
                             FB_SMEM_BYTES);
        dim3 gg(N_ / FB_BN, M_ / FB_BM);
        qkv_gemm_fb<<<gg, 256, FB_SMEM_BYTES>>>(cosb, sinb, bq, bk, bv, out);
    }
}

// round 16
// speedup vs baseline: 1.0003x; 1.0003x over previous
#include <cuda_runtime.h>
#include <cuda_fp16.h>
#include <cstdint>

// Problem constants (Qwen2: B=2, S=4096, H=3584, NH=28, NKV=4, D=128)
#define BB 2
#define SS 4096
#define HH 3584
#define NH 28
#define NKV 4
#define DD 128
#define M_ (BB * SS)                  // 8192
#define N_ ((NH + 2 * NKV) * DD)      // 4608
#define K_ HH                         // 3584
#define QTOT ((size_t)BB * NH * SS * DD)   // 29360128
#define KTOT ((size_t)BB * NKV * SS * DD)  // 4194304

#if defined(__CUDA_ARCH__) && defined(__CUDA_ARCH_HAS_FEATURE__)
#  if __CUDA_ARCH_HAS_FEATURE__(SM103_ALL)
#    define USE_TC 1
#  endif
#endif
#ifndef USE_TC
#  define USE_TC 0
#endif

// ===== persistent cg2 kernel config (round-14 geometry, 6-deep ring) =====
#define P_BK 64                       // one SW128 row
#define P_NKT (K_ / P_BK)             // 56
#define P_NSTAGE 6
#define P_A_BYTES 16384               // A half: 128 rows x 128B
#define P_B_BYTES 16384               // B half: 128 rows x 128B
#define P_STAGE (P_A_BYTES + P_B_BYTES)                   // 32768
#define P_SMEM_DATA 1024
#define P_SMEM_BYTES (P_SMEM_DATA + P_NSTAGE * P_STAGE)   // 197632
#define NPT ((M_ / 256) * (N_ / 256)) // 576 pair-tiles
#define NPAIRS 74
#define NTILE_N (N_ / 256)            // 18

// ===== backup (round-6 proven, 423us) =====
#define TC_BM 256
#define TC_BN 256
#define TC_BK 64
#define TC_NKT (K_ / TC_BK)
#define TC_NSTAGE 3
#define TC_A_BYTES (TC_BM * 128)
#define TC_STAGE_BYTES (TC_A_BYTES + TC_BN * 128)
#define TC_SMEM_DATA 1024
#define TC_SMEM_BYTES (TC_SMEM_DATA + TC_NSTAGE * TC_STAGE_BYTES)

// ===== fallback (round-1 proven) =====
#define FB_BM 128
#define FB_BN 128
#define FB_BK 32
#define FB_BKP (FB_BK + 8)
#define FB_NKT (K_ / FB_BK)
#define FB_SMEM_BYTES 67584

__device__ __half g_A[(size_t)M_ * K_];
__device__ __half g_Wt[(size_t)N_ * K_];
__device__ int g_probe_sink;

struct alignas(64) TMap { unsigned char data[128]; };

extern "C" __attribute__((weak)) int cuTensorMapEncodeTiled(
    void* tensorMap, int tensorDataType, unsigned tensorRank, void* globalAddress,
    const unsigned long long* globalDim, const unsigned long long* globalStrides,
    const unsigned* boxDim, const unsigned* elementStrides,
    int interleave, int swizzle, int l2Promotion, int oobFill);

typedef int (*EncodeFn)(void*, int, unsigned, void*,
                        const unsigned long long*, const unsigned long long*,
                        const unsigned*, const unsigned*, int, int, int, int);

// ---------------------------------------------------------------------------
__global__ void arch_probe(int v) {
#if USE_TC
    __shared__ int buf[512];
#else
    __shared__ int buf[256];
#endif
    buf[threadIdx.x & 255] = v;
    __syncthreads();
    g_probe_sink = buf[(threadIdx.x + (unsigned)v) & 255];
}

// ---------------------------------------------------------------------------
__global__ void convert_hidden(const float* __restrict__ x, int n4) {
    int i = blockIdx.x * blockDim.x + threadIdx.x;
    if (i >= n4) return;
    float4 v = reinterpret_cast<const float4*>(x)[i];
    __half2 h0 = __floats2half2_rn(v.x, v.y);
    __half2 h1 = __floats2half2_rn(v.z, v.w);
    reinterpret_cast<__half2*>(g_A)[2 * i]     = h0;
    reinterpret_cast<__half2*>(g_A)[2 * i + 1] = h1;
}

// ---------------------------------------------------------------------------
__global__ void convert_weights(const float* __restrict__ Wq,
                                const float* __restrict__ Wk,
                                const float* __restrict__ Wv) {
    __shared__ __half tile[32][33];
    int n0 = blockIdx.x * 32;
    int k0 = blockIdx.y * 32;
    int x = threadIdx.x, y = threadIdx.y;

    const float* src;
    int ncols, c0;
    if (n0 < NH * DD)               { src = Wq; ncols = NH * DD;  c0 = n0; }
    else if (n0 < (NH + NKV) * DD)  { src = Wk; ncols = NKV * DD; c0 = n0 - NH * DD; }
    else                            { src = Wv; ncols = NKV * DD; c0 = n0 - (NH + NKV) * DD; }

#pragma unroll
    for (int i = 0; i < 4; i++) {
        int kl = y + i * 8;
        tile[kl][x] = __float2half_rn(src[(size_t)(k0 + kl) * ncols + c0 + x]);
    }
    __syncthreads();
#pragma unroll
    for (int i = 0; i < 4; i++) {
        int nl = y + i * 8;
        g_Wt[(size_t)(n0 + nl) * K_ + k0 + x] = tile[x][nl];
    }
}

// ---------------------------------------------------------------------------
__device__ __forceinline__ uint32_t smem_u32(const void* p) {
    return (uint32_t)__cvta_generic_to_shared(p);
}
__device__ __forceinline__ void cp_async16(void* smem_dst, const void* gsrc) {
    asm volatile("cp.async.cg.shared.global [%0], [%1], 16;\n"
                 :: "r"(smem_u32(smem_dst)), "l"(gsrc));
}

extern __shared__ char smem_raw[];

#if USE_TC
__device__ __forceinline__ uint32_t elect_one_pred() {
    uint32_t pred;
    asm volatile("{\n\t.reg .pred p;\n\telect.sync _|p, 0xFFFFFFFF;\n\t"
                 "selp.b32 %0, 1, 0, p;\n\t}" : "=r"(pred));
    return pred;
}
__device__ __forceinline__ uint32_t cluster_rank() {
    uint32_t r;
    asm("mov.u32 %0, %%cluster_ctarank;" : "=r"(r));
    return r;
}
static constexpr uint64_t DESC_BASE_SW128 =
    (uint64_t(2) << 61) | (uint64_t(1) << 46) | (uint64_t(64) << 32) | (uint64_t(1) << 16);
__device__ __forceinline__ uint64_t make_desc(uint32_t addr) {
    return DESC_BASE_SW128 | ((uint64_t)(addr >> 4) & 0x3FFF);
}
static constexpr uint32_t MMA_IDESC_N128 = (1u << 4) | (16u << 17) | (8u << 24);
// cg2: f16 x f16 -> f32, M=256 (16<<24), N=256 (32<<17)
static constexpr uint32_t MMA_IDESC_CG2  = (1u << 4) | (32u << 17) | (16u << 24);

__device__ __forceinline__ void mma_f16_ss(uint32_t d_tmem, uint64_t a_desc,
                                           uint64_t b_desc, uint32_t idesc,
                                           uint32_t en) {
    asm volatile(
        "{\n\t.reg .pred p;\n\tsetp.ne.u32 p, %5, 0;\n\t"
        "tcgen05.mma.cta_group::1.kind::f16 [%0], %1, %2, %3, {%4, %4, %4, %4}, p;\n\t}"
        :: "r"(d_tmem), "l"(a_desc), "l"(b_desc), "r"(idesc), "r"(0u), "r"(en)
        : "memory");
}
__device__ __forceinline__ void mma_f16_ss_cg2(uint32_t d_tmem, uint64_t a_desc,
                                               uint64_t b_desc, uint32_t en) {
    asm volatile(
        "{\n\t.reg .pred p;\n\tsetp.ne.u32 p, %5, 0;\n\t"
        "tcgen05.mma.cta_group::2.kind::f16 [%0], %1, %2, %3, "
        "{%4, %4, %4, %4, %4, %4, %4, %4}, p;\n\t}"
        :: "r"(d_tmem), "l"(a_desc), "l"(b_desc), "r"(MMA_IDESC_CG2), "r"(0u), "r"(en)
        : "memory");
}
#define TC_ALLOC(smem_addr, ncols) \
    asm volatile("tcgen05.alloc.cta_group::1.sync.aligned.shared::cta.b32 [%0], %1;" \
                 :: "r"(smem_addr), "r"(ncols) : "memory")
#define TC_DEALLOC(tmem, ncols) \
    asm volatile("tcgen05.dealloc.cta_group::1.sync.aligned.b32 %0, %1;" :: "r"(tmem), "r"(ncols))
#define TC_RELINQ() \
    asm volatile("tcgen05.relinquish_alloc_permit.cta_group::1.sync.aligned;")
#define TC_ALLOC_CG2(smem_addr, ncols) \
    asm volatile("tcgen05.alloc.cta_group::2.sync.aligned.shared::cta.b32 [%0], %1;" \
                 :: "r"(smem_addr), "r"(ncols) : "memory")
#define TC_DEALLOC_CG2(tmem, ncols) \
    asm volatile("tcgen05.dealloc.cta_group::2.sync.aligned.b32 %0, %1;" :: "r"(tmem), "r"(ncols))
#define TC_RELINQ_CG2() \
    asm volatile("tcgen05.relinquish_alloc_permit.cta_group::2.sync.aligned;")
#define TC_COMMIT(mbar) \
    asm volatile("tcgen05.commit.cta_group::1.mbarrier::arrive::one.shared::cluster.b64 [%0];" \
                 :: "r"(mbar) : "memory")
#define TC_COMMIT_MC_CG2(mbar, mask) \
    asm volatile("tcgen05.commit.cta_group::2.mbarrier::arrive::one.shared::cluster.multicast::cluster.b64 [%0], %1;" \
                 :: "r"(mbar), "h"((uint16_t)(mask)) : "memory")
#define TC_FENCE_AFTER()  asm volatile("tcgen05.fence::after_thread_sync;" ::: "memory")
#define TC_WAIT_LD() asm volatile("tcgen05.wait::ld.sync.aligned;" ::: "memory")
#define MBAR_INIT(mbar, cnt) \
    asm volatile("mbarrier.init.shared.b64 [%0], %1;" :: "r"(mbar), "r"(cnt) : "memory")
#define MBAR_EXPECT_TX(mbar, bytes) \
    asm volatile("mbarrier.arrive.expect_tx.shared.b64 _, [%0], %1;" \
                 :: "r"(mbar), "r"(bytes) : "memory")
#define MBAR_ARRIVE(mbar) \
    asm volatile("mbarrier.arrive.shared.b64 _, [%0];" :: "r"(mbar) : "memory")
#define MBAR_ARRIVE_CLUSTER(local_mbar, target_rank) \
    asm volatile( \
        "{\n\t.reg .b32 remAddr;\n\t" \
        "mapa.shared::cluster.u32 remAddr, %0, %1;\n\t" \
        "mbarrier.arrive.shared::cluster.b64 _, [remAddr];\n\t}" \
        :: "r"(local_mbar), "r"(target_rank) : "memory")
#define FENCE_ASYNC_SHARED() asm volatile("fence.proxy.async.shared::cta;" ::: "memory")
#define CLUSTER_SYNC() do { \
    asm volatile("barrier.cluster.arrive.aligned;" ::: "memory"); \
    asm volatile("barrier.cluster.wait.aligned;" ::: "memory"); \
} while (0)

// cg2 TMA: dest local SMEM, complete_tx to LEADER's barrier (bit 24 cleared).
__device__ __forceinline__ void tma_load_3d_cg2(uint32_t smem_addr, const void* tmap,
                                                int cx, int cy, uint32_t mbar) {
    asm volatile(
        "{\n\t.reg .b32 lb;\n\t"
        "and.b32 lb, %4, 0xFEFFFFFF;\n\t"
        "cp.async.bulk.tensor.3d.cta_group::2.shared::cluster.global"
        ".tile.mbarrier::complete_tx::bytes [%0], [%1, {%2, %3, 0}], [lb];\n\t}"
        :: "r"(smem_addr), "l"(tmap), "r"(cx), "r"(cy), "r"(mbar) : "memory");
}

#define LDTM_X32(r, addr) \
    asm volatile( \
        "tcgen05.ld.sync.aligned.32x32b.x32.b32 " \
        "{%0, %1, %2, %3, %4, %5, %6, %7, " \
        " %8, %9, %10, %11, %12, %13, %14, %15, " \
        " %16, %17, %18, %19, %20, %21, %22, %23, " \
        " %24, %25, %26, %27, %28, %29, %30, %31}, [%32];" \
        : "=r"((r)[0]),  "=r"((r)[1]),  "=r"((r)[2]),  "=r"((r)[3]), \
          "=r"((r)[4]),  "=r"((r)[5]),  "=r"((r)[6]),  "=r"((r)[7]), \
          "=r"((r)[8]),  "=r"((r)[9]),  "=r"((r)[10]), "=r"((r)[11]), \
          "=r"((r)[12]), "=r"((r)[13]), "=r"((r)[14]), "=r"((r)[15]), \
          "=r"((r)[16]), "=r"((r)[17]), "=r"((r)[18]), "=r"((r)[19]), \
          "=r"((r)[20]), "=r"((r)[21]), "=r"((r)[22]), "=r"((r)[23]), \
          "=r"((r)[24]), "=r"((r)[25]), "=r"((r)[26]), "=r"((r)[27]), \
          "=r"((r)[28]), "=r"((r)[29]), "=r"((r)[30]), "=r"((r)[31]) \
        : "r"(addr))

__device__ __forceinline__ void mbar_wait_parity(uint32_t mbar, uint32_t parity) {
    asm volatile(
        "{\n\t.reg .pred P1;\n\t"
        "WAIT_LOOP_%=:\n\t"
        "mbarrier.try_wait.parity.acquire.cta.shared::cta.b64 P1, [%0], %1, 0x989680;\n\t"
        "@P1 bra.uni WAIT_DONE_%=;\n\t"
        "bra.uni WAIT_LOOP_%=;\n\t"
        "WAIT_DONE_%=:\n\t}"
        :: "r"(mbar), "r"(parity) : "memory");
}

// Epilogue for a local BM=128 x BN=256 half-tile (round-12 proven mapping).
__device__ __forceinline__ void p_epilogue(
    uint32_t dtmem, int wid, int lane, int m0, int n0,
    const float* cosb, const float* sinb,
    const float* bq, const float* bk, const float* bv, float* out) {
    const int row = ((wid & 3) << 5) + lane;
    const int m = m0 + row;
    const int bt = m >> 12;
    const int s  = m & 4095;
    const int nbase = n0 + (wid >> 2) * 128;
    const int head = nbase >> 7;
    const bool isq = head < NH;
    const bool isk = (head >= NH) && (head < NH + NKV);
    const float* bias;
    size_t obase;
    if (isq)      { bias = bq + nbase;
                    obase = (((size_t)bt * NH + head) * SS + s) * DD; }
    else if (isk) { bias = bk + (nbase - NH * DD);
                    obase = QTOT + (((size_t)bt * NKV + (head - NH)) * SS + s) * DD; }
    else          { bias = bv + (nbase - (NH + NKV) * DD);
                    obase = QTOT + KTOT + (((size_t)bt * NKV + (head - NH - NKV)) * SS + s) * DD; }
    const uint32_t dbase = dtmem + (wid >> 2) * 128;

#pragma unroll
    for (int half = 0; half < 2; half++) {
        uint32_t rlo[32], rhi[32];
        LDTM_X32(rlo, dbase + half * 32);
        LDTM_X32(rhi, dbase + half * 32 + 64);
        TC_WAIT_LD();

        float vlo[32], vhi[32];
#pragma unroll
        for (int i = 0; i < 32; i++) {
            vlo[i] = __uint_as_float(rlo[i]) + bias[half * 32 + i];
            vhi[i] = __uint_as_float(rhi[i]) + bias[half * 32 + 64 + i];
        }
        if (isq || isk) {
            const float* cp = cosb + (size_t)m * DD + half * 32;
            const float* sp = sinb + (size_t)m * DD + half * 32;
#pragma unroll
            for (int i = 0; i < 32; i++) {
                float c = cp[i], sn = sp[i];
                float lo = vlo[i] * c - vhi[i] * sn;
                float hi = vhi[i] * c + vlo[i] * sn;
                vlo[i] = lo; vhi[i] = hi;
            }
        }
        float* o = out + obase + half * 32;
#pragma unroll
        for (int i = 0; i < 8; i++) {
            *reinterpret_cast<float4*>(o + i * 4) =
                make_float4(vlo[i*4], vlo[i*4+1], vlo[i*4+2], vlo[i*4+3]);
            *reinterpret_cast<float4*>(o + 64 + i * 4) =
                make_float4(vhi[i*4], vhi[i*4+1], vhi[i*4+2], vhi[i*4+3]);
        }
    }
}

// Big-tile epilogue for the backup kernel (round-6 proven).
__device__ __forceinline__ void tc_epilogue(
    uint32_t tmem_base, int wid, int lane, int m0, int n0,
    const float* cosb, const float* sinb,
    const float* bq, const float* bk, const float* bv, float* out) {
    const int sub = wid >> 2;
    const int row = ((wid & 3) << 5) + lane;
    const int m = m0 + sub * 128 + row;
    const int bt = m >> 12;
    const int s  = m & 4095;
    const uint32_t dbase = tmem_base + sub * 256;

#pragma unroll
    for (int hc = 0; hc < 2; hc++) {
        const int nbase = n0 + hc * 128;
        const int head = nbase >> 7;
        const bool isq = head < NH;
        const bool isk = (head >= NH) && (head < NH + NKV);
        const float* bias;
        size_t obase;
        if (isq)      { bias = bq + nbase;
                        obase = (((size_t)bt * NH + head) * SS + s) * DD; }
        else if (isk) { bias = bk + (nbase - NH * DD);
                        obase = QTOT + (((size_t)bt * NKV + (head - NH)) * SS + s) * DD; }
        else          { bias = bv + (nbase - (NH + NKV) * DD);
                        obase = QTOT + KTOT + (((size_t)bt * NKV + (head - NH - NKV)) * SS + s) * DD; }

#pragma unroll
        for (int half = 0; half < 2; half++) {
            uint32_t rlo[32], rhi[32];
            LDTM_X32(rlo, dbase + hc * 128 + half * 32);
            LDTM_X32(rhi, dbase + hc * 128 + half * 32 + 64);
            TC_WAIT_LD();

            float vlo[32], vhi[32];
#pragma unroll
            for (int i = 0; i < 32; i++) {
                vlo[i] = __uint_as_float(rlo[i]) + bias[half * 32 + i];
                vhi[i] = __uint_as_float(rhi[i]) + bias[half * 32 + 64 + i];
            }
            if (isq || isk) {
                const float* cp = cosb + (size_t)m * DD + half * 32;
                const float* sp = sinb + (size_t)m * DD + half * 32;
#pragma unroll
                for (int i = 0; i < 32; i++) {
                    float c = cp[i], sn = sp[i];
                    float lo = vlo[i] * c - vhi[i] * sn;
                    float hi = vhi[i] * c + vlo[i] * sn;
                    vlo[i] = lo; vhi[i] = hi;
                }
            }
            float* o = out + obase + half * 32;
#pragma unroll
            for (int i = 0; i < 8; i++) {
                *reinterpret_cast<float4*>(o + i * 4) =
                    make_float4(vlo[i*4], vlo[i*4+1], vlo[i*4+2], vlo[i*4+3]);
                *reinterpret_cast<float4*>(o + 64 + i * 4) =
                    make_float4(vhi[i*4], vhi[i*4+1], vhi[i*4+2], vhi[i*4+3]);
            }
        }
    }
}
#endif  // USE_TC

// ===========================================================================
// PRIMARY: persistent cluster(2,1,1) cta_group::2 tcgen05 kernel.
// ROUND-14 WINNER (290us) with the stage ring deepened 4 -> 6.
// grid (2, 74) = 148 persistent CTAs, pair = blockIdx.y, rank along x.
// Pair tile = M256 x N256. Each CTA holds A-half + B-half (no replication).
// All 4 TMA loads complete_tx on LEADER's FULL bar (expect_tx 64KB).
// Leader (rank 0) issues cg2 MMA; commit.cg2 multicast releases both CTAs.
// TMEM halves 0/256 double-buffered: epilogue(t) overlaps mainloop(t+1).
// Warps 0-7: epilogue. Warp 8 lane0: producer. Warp 9 lane0 (leader): MMA.
// mbars: FULL(s)=+16+s*16 cnt1, EMPTY(s)=+24+s*16 cnt1 (s=0..5 -> +16..+111),
//        MDONE[h]=+128+h*8 cnt1, EDONE[h]=+144+h*8 cnt16 (leader).
// ===========================================================================
__global__ __launch_bounds__(320, 1) __cluster_dims__(2, 1, 1)
void qkv_gemm_tma(const __grid_constant__ TMap tma_a,
                  const __grid_constant__ TMap tma_b,
                  const float* __restrict__ cosb, const float* __restrict__ sinb,
                  const float* __restrict__ bq, const float* __restrict__ bk,
                  const float* __restrict__ bv, float* __restrict__ out) {
#if USE_TC
    const int tid  = threadIdx.x;
    const int wid  = tid >> 5, lane = tid & 31;
    const uint32_t rank = cluster_rank();      // 0/1 along x
    const int pair = blockIdx.y;

    const uint32_t smem_base = smem_u32(smem_raw);
    const uint32_t FULL0 = smem_base + 16, EMPTY0 = smem_base + 24;
    const uint32_t MDONE0 = smem_base + 128, EDONE0 = smem_base + 144;

    if (wid == 0) TC_ALLOC_CG2(smem_base, 512);
    if (tid == 0) {
#pragma unroll
        for (int s = 0; s < P_NSTAGE; s++) {
            MBAR_INIT(FULL0 + s * 16, 1);     // leader: expect_tx arrival
            MBAR_INIT(EMPTY0 + s * 16, 1);    // one cg2 commit-mc arrival
        }
        MBAR_INIT(MDONE0, 1);     MBAR_INIT(MDONE0 + 8, 1);
        MBAR_INIT(EDONE0, 16);    MBAR_INIT(EDONE0 + 8, 16);  // 8 warps x 2 CTAs
    }
    __syncthreads();
    CLUSTER_SYNC();

    uint32_t tmem_base;
    asm volatile("ld.shared.b32 %0, [%1];" : "=r"(tmem_base) : "r"(smem_base));

    if (tid == 256) {
        // ================= TMA producer (both CTAs) =================
        uint32_t pph = 1;
        int slot = 0;
        for (int pt = pair; pt < NPT; pt += NPAIRS) {
            const int m0 = (pt / NTILE_N) * 256 + (int)rank * 128;  // my A half
            const int n0 = (pt % NTILE_N) * 256 + (int)rank * 128;  // my B half
            for (int kt = 0; kt < P_NKT; kt++) {
                mbar_wait_parity(EMPTY0 + slot * 16, pph);
                uint32_t sa = smem_base + P_SMEM_DATA + slot * P_STAGE;
                if (rank == 0)
                    MBAR_EXPECT_TX(FULL0 + slot * 16, 2 * P_STAGE);  // 64KB total
                tma_load_3d_cg2(sa, &tma_a, kt * P_BK, m0, FULL0 + slot * 16);
                tma_load_3d_cg2(sa + P_A_BYTES, &tma_b, kt * P_BK, n0,
                                FULL0 + slot * 16);
                if (++slot == P_NSTAGE) { slot = 0; pph ^= 1; }
            }
        }
    } else if (tid == 288 && rank == 0) {
        // ================= MMA issuer (leader only) =================
        uint32_t cph = 0;
        int slot = 0;
        uint32_t eph[2] = {1, 1};
        int ti = 0;
        for (int pt = pair; pt < NPT; pt += NPAIRS) {
            const int half = ti & 1;
            mbar_wait_parity(EDONE0 + half * 8, eph[half]);  // both epilogues done
            eph[half] ^= 1;
            const uint32_t dt = tmem_base + half * 256;
            for (int kt = 0; kt < P_NKT; kt++) {
                mbar_wait_parity(FULL0 + slot * 16, cph);
                uint32_t sa = smem_base + P_SMEM_DATA + slot * P_STAGE;
                uint64_t ad = make_desc(sa);               // A halves in both CTAs
                uint64_t bd = make_desc(sa + P_A_BYTES);   // B halves in both CTAs
#pragma unroll
                for (int ks = 0; ks < 4; ks++) {
                    uint32_t en = (kt > 0 || ks > 0) ? 1u : 0u;
                    mma_f16_ss_cg2(dt, ad + ks * 2, bd + ks * 2, en);
                }
                TC_COMMIT_MC_CG2(EMPTY0 + slot * 16, 0x3);
                if (++slot == P_NSTAGE) { slot = 0; cph ^= 1; }
            }
            TC_COMMIT_MC_CG2(MDONE0 + half * 8, 0x3);     // tile done, both CTAs
            ti++;
        }
    } else if (wid < 8) {
        // ================= epilogue warps (both CTAs) =================
        uint32_t mph[2] = {0, 0};
        int ti = 0;
        for (int pt = pair; pt < NPT; pt += NPAIRS) {
            const int half = ti & 1;
            const int m0 = (pt / NTILE_N) * 256 + (int)rank * 128;
            const int n0 = (pt % NTILE_N) * 256;
            mbar_wait_parity(MDONE0 + half * 8, mph[half]);
            mph[half] ^= 1;
            TC_FENCE_AFTER();
            p_epilogue(tmem_base + half * 256, wid, lane, m0, n0,
                       cosb, sinb, bq, bk, bv, out);
            if (lane == 0) MBAR_ARRIVE_CLUSTER(EDONE0 + half * 8, 0u);  // leader's bar
            ti++;
        }
    }

    __syncthreads();
    CLUSTER_SYNC();
    if (wid == 0) {
        TC_RELINQ_CG2();
        TC_DEALLOC_CG2(tmem_base, 512);
    }
    CLUSTER_SYNC();
#endif  // USE_TC
}

// ===========================================================================
// cp.async tcgen05 kernel — ROUND-6 PROVEN (423 us) backup. grid (18, 32).
// ===========================================================================
__global__ __launch_bounds__(256, 1)
void qkv_gemm_tc(const float* __restrict__ cosb, const float* __restrict__ sinb,
                 const float* __restrict__ bq, const float* __restrict__ bk,
                 const float* __restrict__ bv, float* __restrict__ out) {
#if USE_TC
    const int tid  = threadIdx.x;
    const int wid  = tid >> 5, lane = tid & 31;
    const int m0 = blockIdx.y * TC_BM;
    const int n0 = blockIdx.x * TC_BN;

    const uint32_t smem_base = smem_u32(smem_raw);
    const uint32_t mbar = smem_base + 8;

    if (wid == 0) TC_ALLOC(smem_base, 512);
    if (tid == 0) MBAR_INIT(mbar, 1);
    __syncthreads();
    uint32_t tmem_base;
    asm volatile("ld.shared.b32 %0, [%1];" : "=r"(tmem_base) : "r"(smem_base));

    const int lc = tid & 7;
    const int lr = tid >> 3;
    auto load_tile = [&](int buf, int kt) {
        char* sb = smem_raw + TC_SMEM_DATA + buf * TC_STAGE_BYTES;
        const __half* Ag = g_A + (size_t)(m0 + lr) * K_ + kt * TC_BK + lc * 8;
#pragma unroll
        for (int i = 0; i < 8; i++) {
            int row = lr + i * 32;
            uint32_t off = row * 128 + ((lc ^ (row & 7)) * 16);
            cp_async16(sb + off, Ag + (size_t)(i * 32) * K_);
        }
        const __half* Bg = g_Wt + (size_t)(n0 + lr) * K_ + kt * TC_BK + lc * 8;
#pragma unroll
        for (int i = 0; i < 8; i++) {
            int row = lr + i * 32;
            uint32_t off = TC_A_BYTES + row * 128 + ((lc ^ (row & 7)) * 16);
            cp_async16(sb + off, Bg + (size_t)(i * 32) * K_);
        }
    };

    load_tile(0, 0);
    asm volatile("cp.async.commit_group;\n");
    load_tile(1, 1);
    asm volatile("cp.async.commit_group;\n");

    uint32_t ph = 0;
    for (int kt = 0; kt < TC_NKT; kt++) {
        if (kt + 1 < TC_NKT) {
            asm volatile("cp.async.wait_group 1;\n");
        } else {
            asm volatile("cp.async.wait_group 0;\n");
        }
        __syncthreads();

        if (wid == 0) {
            FENCE_ASYNC_SHARED();
            if (elect_one_pred()) {
                uint32_t sa = smem_base + TC_SMEM_DATA + (kt % TC_NSTAGE) * TC_STAGE_BYTES;
                uint64_t ad0 = make_desc(sa);
                uint64_t ad1 = make_desc(sa + 16384);
                uint64_t bd0 = make_desc(sa + TC_A_BYTES);
                uint64_t bd1 = make_desc(sa + TC_A_BYTES + 16384);
#pragma unroll
                for (int ks = 0; ks < 4; ks++) {
                    uint32_t en = (kt > 0 || ks > 0) ? 1u : 0u;
                    mma_f16_ss(tmem_base,       ad0 + ks * 2, bd0 + ks * 2, MMA_IDESC_N128, en);
                    mma_f16_ss(tmem_base + 128, ad0 + ks * 2, bd1 + ks * 2, MMA_IDESC_N128, en);
                    mma_f16_ss(tmem_base + 256, ad1 + ks * 2, bd0 + ks * 2, MMA_IDESC_N128, en);
                    mma_f16_ss(tmem_base + 384, ad1 + ks * 2, bd1 + ks * 2, MMA_IDESC_N128, en);
                }
                TC_COMMIT(mbar);
            }
        }
        if (kt >= 1) { mbar_wait_parity(mbar, ph); ph ^= 1; }

        if (kt + 2 < TC_NKT) {
            load_tile((kt + 2) % TC_NSTAGE, kt + 2);
            asm volatile("cp.async.commit_group;\n");
        }
    }
    mbar_wait_parity(mbar, ph);
    TC_FENCE_AFTER();

    tc_epilogue(tmem_base, wid, lane, m0, n0, cosb, sinb, bq, bk, bv, out);

    __syncthreads();
    if (wid == 0) {
        TC_RELINQ();
        TC_DEALLOC(tmem_base, 512);
    }
#endif  // USE_TC
}

// ===========================================================================
// Fallback kernel — ROUND-1 PROVEN CODE, VERBATIM SEMANTICS.
// ===========================================================================
__device__ __forceinline__ void ldsm_x4(uint32_t& r0, uint32_t& r1, uint32_t& r2,
                                        uint32_t& r3, const void* p) {
    uint32_t a = (uint32_t)__cvta_generic_to_shared(p);
    asm volatile("ldmatrix.sync.aligned.m8n8.x4.shared.b16 {%0,%1,%2,%3}, [%4];\n"
                 : "=r"(r0), "=r"(r1), "=r"(r2), "=r"(r3) : "r"(a));
}
__device__ __forceinline__ void mma16816(float* c, const uint32_t* a, const uint32_t* b) {
    asm volatile(
        "mma.sync.aligned.m16n8k16.row.col.f32.f16.f16.f32 "
        "{%0,%1,%2,%3}, {%4,%5,%6,%7}, {%8,%9}, {%0,%1,%2,%3};\n"
        : "+f"(c[0]), "+f"(c[1]), "+f"(c[2]), "+f"(c[3])
        : "r"(a[0]), "r"(a[1]), "r"(a[2]), "r"(a[3]), "r"(b[0]), "r"(b[1]));
}

__global__ __launch_bounds__(256, 2) void qkv_gemm_fb(
    const float* __restrict__ cosb, const float* __restrict__ sinb,
    const float* __restrict__ bq, const float* __restrict__ bk,
    const float* __restrict__ bv, float* __restrict__ out) {

    __half (*As)[FB_BM][FB_BKP] = reinterpret_cast<__half (*)[FB_BM][FB_BKP]>(smem_raw);
    __half (*Bs)[FB_BN][FB_BKP] =
        reinterpret_cast<__half (*)[FB_BN][FB_BKP]>(smem_raw + 2 * FB_BM * FB_BKP * 2);

    const int tid  = threadIdx.x;
    const int warp = tid >> 5, lane = tid & 31;
    const int wm = warp & 3, wn = warp >> 2;
    const int tileN = blockIdx.x;
    const int m0 = blockIdx.y * FB_BM;
    const int n0 = tileN * FB_BN;

    const int lrow = tid >> 2;
    const int lch  = tid & 3;

    float acc[2][8][4];
#pragma unroll
    for (int i = 0; i < 2; i++)
#pragma unroll
        for (int j = 0; j < 8; j++)
#pragma unroll
            for (int l = 0; l < 4; l++) acc[i][j][l] = 0.f;

    auto load_tile = [&](int buf, int kt) {
        const __half* Ag = g_A + (size_t)(m0 + lrow) * K_ + kt * FB_BK + lch * 8;
        cp_async16(&As[buf][lrow][lch * 8], Ag);
        cp_async16(&As[buf][lrow + 64][lch * 8], Ag + (size_t)64 * K_);
        const __half* Bg = g_Wt + (size_t)(n0 + lrow) * K_ + kt * FB_BK + lch * 8;
        cp_async16(&Bs[buf][lrow][lch * 8], Bg);
        cp_async16(&Bs[buf][lrow + 64][lch * 8], Bg + (size_t)64 * K_);
    };

    load_tile(0, 0);
    asm volatile("cp.async.commit_group;\n");

    for (int kt = 0; kt < FB_NKT; kt++) {
        asm volatile("cp.async.wait_group 0;\n");
        __syncthreads();
        if (kt + 1 < FB_NKT) {
            load_tile((kt + 1) & 1, kt + 1);
            asm volatile("cp.async.commit_group;\n");
        }
        const int buf = kt & 1;

#pragma unroll
        for (int ks = 0; ks < 2; ks++) {
            uint32_t a[2][4];
            uint32_t b[8][2];
            const int kc = ks * 16 + (lane >> 4) * 8;
            const int rsel = lane & 15;
#pragma unroll
            for (int fm = 0; fm < 2; fm++)
                ldsm_x4(a[fm][0], a[fm][1], a[fm][2], a[fm][3],
                        &As[buf][wm * 32 + fm * 16 + rsel][kc]);
#pragma unroll
            for (int g = 0; g < 4; g++) {
                uint32_t t0, t1, t2, t3;
                ldsm_x4(t0, t1, t2, t3, &Bs[buf][wn * 64 + g * 16 + rsel][kc]);
                b[g * 2][0] = t0;     b[g * 2][1] = t2;
                b[g * 2 + 1][0] = t1; b[g * 2 + 1][1] = t3;
            }
#pragma unroll
            for (int fm = 0; fm < 2; fm++)
#pragma unroll
                for (int fn = 0; fn < 8; fn++)
                    mma16816(acc[fm][fn], a[fm], b[fn]);
        }
    }

    __syncthreads();
    float (*Cs)[132] = reinterpret_cast<float (*)[132]>(smem_raw);
#pragma unroll
    for (int fm = 0; fm < 2; fm++) {
        int r = wm * 32 + fm * 16 + (lane >> 2);
#pragma unroll
        for (int fn = 0; fn < 8; fn++) {
            int c = wn * 64 + fn * 8 + (lane & 3) * 2;
            Cs[r][c]         = acc[fm][fn][0];
            Cs[r][c + 1]     = acc[fm][fn][1];
            Cs[r + 8][c]     = acc[fm][fn][2];
            Cs[r + 8][c + 1] = acc[fm][fn][3];
        }
    }
    __syncthreads();

    const bool is_q = (tileN < NH);
    const bool is_k = (tileN >= NH) && (tileN < NH + NKV);
    const float* bias;
    if (is_q)       bias = bq + n0;
    else if (is_k)  bias = bk + (n0 - NH * DD);
    else            bias = bv + (n0 - (NH + NKV) * DD);

#pragma unroll 4
    for (int it = 0; it < 16; it++) {
        int r = (tid >> 5) + it * 8;
        int c = (tid & 31) * 4;
        int m = m0 + r;
        int bt = m >> 12;
        int s  = m & 4095;

        float vv[4];
        if (is_q || is_k) {
#pragma unroll
            for (int j = 0; j < 4; j++) {
                int cj = c + j;
                float val = Cs[r][cj] + bias[cj];
                float pr  = Cs[r][cj ^ 64] + bias[cj ^ 64];
                float cse = cosb[(size_t)m * DD + cj];
                float sne = sinb[(size_t)m * DD + cj];
                float rot = (cj < 64) ? -pr : pr;
                vv[j] = val * cse + rot * sne;
            }
        } else {
#pragma unroll
            for (int j = 0; j < 4; j++) vv[j] = Cs[r][c + j] + bias[c + j];
        }

        size_t off;
        if (is_q)
            off = (((size_t)bt * NH + tileN) * SS + s) * DD + c;
        else if (is_k)
            off = QTOT + (((size_t)bt * NKV + (tileN - NH)) * SS + s) * DD + c;
        else
            off = QTOT + KTOT + (((size_t)bt * NKV + (tileN - NH - NKV)) * SS + s) * DD + c;

        *reinterpret_cast<float4*>(out + off) = make_float4(vv[0], vv[1], vv[2], vv[3]);
    }
}

// ---------------------------------------------------------------------------
extern "C" void kernel_launch(void* const* d_in, const int* in_sizes, int n_in,
                              void* d_out, int out_size) {
    const float* hs   = (const float*)d_in[0];
    const float* cosb = (const float*)d_in[1];
    const float* sinb = (const float*)d_in[2];
    const float* Wq   = (const float*)d_in[3];
    const float* bq   = (const float*)d_in[4];
    const float* Wk   = (const float*)d_in[5];
    const float* bk   = (const float*)d_in[6];
    const float* Wv   = (const float*)d_in[7];
    const float* bv   = (const float*)d_in[8];
    float* out = (float*)d_out;

    cudaFuncAttributes pa;
    bool use_tc = false;
    if (cudaFuncGetAttributes(&pa, arch_probe) == cudaSuccess)
        use_tc = (pa.sharedSizeBytes >= 2048);

    int n4 = (M_ * K_) / 4;
    convert_hidden<<<(n4 + 255) / 256, 256>>>(hs, n4);

    dim3 gw(N_ / 32, K_ / 32);
    convert_weights<<<gw, dim3(32, 8)>>>(Wq, Wk, Wv);

    if (use_tc) {
        EncodeFn enc = nullptr;
        {
            void* p = nullptr;
            cudaDriverEntryPointQueryResult st;
            if (cudaGetDriverEntryPoint("cuTensorMapEncodeTiled", &p,
                                        cudaEnableDefault, &st) == cudaSuccess &&
                st == cudaDriverEntryPointSuccess && p)
                enc = (EncodeFn)p;
        }
        if (!enc && &cuTensorMapEncodeTiled != nullptr)
            enc = (EncodeFn)cuTensorMapEncodeTiled;

        bool tma_ok = false;
        TMap ta, tb;
        if (enc) {
            void* pA = nullptr; void* pB = nullptr;
            cudaGetSymbolAddress(&pA, g_A);
            cudaGetSymbolAddress(&pB, g_Wt);
            if (pA && pB) {
                unsigned long long dimsA[3] = { (unsigned long long)K_, (unsigned long long)M_, 1 };
                unsigned long long dimsB[3] = { (unsigned long long)K_, (unsigned long long)N_, 1 };
                unsigned long long strA[2]  = { (unsigned long long)K_ * 2,
                                                (unsigned long long)K_ * 2 * M_ };
                unsigned long long strB[2]  = { (unsigned long long)K_ * 2,
                                                (unsigned long long)K_ * 2 * N_ };
                unsigned boxH[3] = { P_BK, 128, 1 };   // 64-half x 128-row tiles
                unsigned es[3] = { 1, 1, 1 };
                int r1 = enc(&ta, 6, 3, pA, dimsA, strA, boxH, es, 0, 3, 2, 0);
                int r2 = enc(&tb, 6, 3, pB, dimsB, strB, boxH, es, 0, 3, 2, 0);
                tma_ok = (r1 == 0 && r2 == 0);
            }
        }
        if (tma_ok) {
            cudaFuncSetAttribute(qkv_gemm_tma, cudaFuncAttributeMaxDynamicSharedMemorySize,
                                 P_SMEM_BYTES);
            dim3 gg(2, NPAIRS);                // 148 persistent CTAs, cluster (2,1,1)
            qkv_gemm_tma<<<gg, 320, P_SMEM_BYTES>>>(ta, tb, cosb, sinb, bq, bk, bv, out);
        } else {
            cudaFuncSetAttribute(qkv_gemm_tc, cudaFuncAttributeMaxDynamicSharedMemorySize,
                                 TC_SMEM_BYTES);
            dim3 gg(N_ / TC_BN, M_ / TC_BM);
            qkv_gemm_tc<<<gg, 256, TC_SMEM_BYTES>>>(cosb, sinb, bq, bk, bv, out);
        }
    } else {
        cudaFuncSetAttribute(qkv_gemm_fb, cudaFuncAttributeMaxDynamicSharedMemorySize,
                             FB_SMEM_BYTES);
        dim3 gg(N_ / FB_BN, M_ / FB_BM);
        qkv_gemm_fb<<<gg, 256, FB_SMEM_BYTES>>>(cosb, sinb, bq, bk, bv, out);
    }
}

// round 17
// speedup vs baseline: 1.0581x; 1.0578x over previous
#include <cuda_runtime.h>
#include <cuda_fp16.h>
#include <cstdint>

// Problem constants (Qwen2: B=2, S=4096, H=3584, NH=28, NKV=4, D=128)
#define BB 2
#define SS 4096
#define HH 3584
#define NH 28
#define NKV 4
#define DD 128
#define M_ (BB * SS)                  // 8192
#define N_ ((NH + 2 * NKV) * DD)      // 4608
#define K_ HH                         // 3584
#define QTOT ((size_t)BB * NH * SS * DD)   // 29360128
#define KTOT ((size_t)BB * NKV * SS * DD)  // 4194304

#if defined(__CUDA_ARCH__) && defined(__CUDA_ARCH_HAS_FEATURE__)
#  if __CUDA_ARCH_HAS_FEATURE__(SM103_ALL)
#    define USE_TC 1
#  endif
#endif
#ifndef USE_TC
#  define USE_TC 0
#endif

// ===== persistent cg2 kernel config — ROUND-14 WINNER GEOMETRY (290.3us) =====
#define P_BK 64                       // one SW128 row
#define P_NKT (K_ / P_BK)             // 56
#define P_NSTAGE 4
#define P_A_BYTES 16384               // A half: 128 rows x 128B
#define P_B_BYTES 16384               // B half: 128 rows x 128B
#define P_STAGE (P_A_BYTES + P_B_BYTES)                   // 32768
#define P_SMEM_DATA 1024
#define P_SMEM_BYTES (P_SMEM_DATA + P_NSTAGE * P_STAGE)   // 132096
#define NPT ((M_ / 256) * (N_ / 256)) // 576 pair-tiles
#define NPAIRS 74
#define NTILE_N (N_ / 256)            // 18

// ===== backup (round-6 proven, 423us) =====
#define TC_BM 256
#define TC_BN 256
#define TC_BK 64
#define TC_NKT (K_ / TC_BK)
#define TC_NSTAGE 3
#define TC_A_BYTES (TC_BM * 128)
#define TC_STAGE_BYTES (TC_A_BYTES + TC_BN * 128)
#define TC_SMEM_DATA 1024
#define TC_SMEM_BYTES (TC_SMEM_DATA + TC_NSTAGE * TC_STAGE_BYTES)

// ===== fallback (round-1 proven) =====
#define FB_BM 128
#define FB_BN 128
#define FB_BK 32
#define FB_BKP (FB_BK + 8)
#define FB_NKT (K_ / FB_BK)
#define FB_SMEM_BYTES 67584

__device__ __half g_A[(size_t)M_ * K_];
__device__ __half g_Wt[(size_t)N_ * K_];
__device__ int g_probe_sink;

struct alignas(64) TMap { unsigned char data[128]; };

extern "C" __attribute__((weak)) int cuTensorMapEncodeTiled(
    void* tensorMap, int tensorDataType, unsigned tensorRank, void* globalAddress,
    const unsigned long long* globalDim, const unsigned long long* globalStrides,
    const unsigned* boxDim, const unsigned* elementStrides,
    int interleave, int swizzle, int l2Promotion, int oobFill);

typedef int (*EncodeFn)(void*, int, unsigned, void*,
                        const unsigned long long*, const unsigned long long*,
                        const unsigned*, const unsigned*, int, int, int, int);

// ---------------------------------------------------------------------------
__global__ void arch_probe(int v) {
#if USE_TC
    __shared__ int buf[512];
#else
    __shared__ int buf[256];
#endif
    buf[threadIdx.x & 255] = v;
    __syncthreads();
    g_probe_sink = buf[(threadIdx.x + (unsigned)v) & 255];
}

// ---------------------------------------------------------------------------
// fp32 -> fp16 convert, 8 floats per thread (2x float4 read, 1x uint4 write)
// ---------------------------------------------------------------------------
__global__ void convert_hidden(const float* __restrict__ x, int n8) {
    int i = blockIdx.x * blockDim.x + threadIdx.x;
    if (i >= n8) return;
    const float4* p = reinterpret_cast<const float4*>(x) + 2 * (size_t)i;
    float4 a = p[0];
    float4 b = p[1];
    __half2 h0 = __floats2half2_rn(a.x, a.y);
    __half2 h1 = __floats2half2_rn(a.z, a.w);
    __half2 h2 = __floats2half2_rn(b.x, b.y);
    __half2 h3 = __floats2half2_rn(b.z, b.w);
    uint4 o;
    o.x = *reinterpret_cast<uint32_t*>(&h0);
    o.y = *reinterpret_cast<uint32_t*>(&h1);
    o.z = *reinterpret_cast<uint32_t*>(&h2);
    o.w = *reinterpret_cast<uint32_t*>(&h3);
    reinterpret_cast<uint4*>(g_A)[i] = o;
}

// ---------------------------------------------------------------------------
__global__ void convert_weights(const float* __restrict__ Wq,
                                const float* __restrict__ Wk,
                                const float* __restrict__ Wv) {
    __shared__ __half tile[32][33];
    int n0 = blockIdx.x * 32;
    int k0 = blockIdx.y * 32;
    int x = threadIdx.x, y = threadIdx.y;

    const float* src;
    int ncols, c0;
    if (n0 < NH * DD)               { src = Wq; ncols = NH * DD;  c0 = n0; }
    else if (n0 < (NH + NKV) * DD)  { src = Wk; ncols = NKV * DD; c0 = n0 - NH * DD; }
    else                            { src = Wv; ncols = NKV * DD; c0 = n0 - (NH + NKV) * DD; }

#pragma unroll
    for (int i = 0; i < 4; i++) {
        int kl = y + i * 8;
        tile[kl][x] = __float2half_rn(src[(size_t)(k0 + kl) * ncols + c0 + x]);
    }
    __syncthreads();
#pragma unroll
    for (int i = 0; i < 4; i++) {
        int nl = y + i * 8;
        g_Wt[(size_t)(n0 + nl) * K_ + k0 + x] = tile[x][nl];
    }
}

// ---------------------------------------------------------------------------
__device__ __forceinline__ uint32_t smem_u32(const void* p) {
    return (uint32_t)__cvta_generic_to_shared(p);
}
__device__ __forceinline__ void cp_async16(void* smem_dst, const void* gsrc) {
    asm volatile("cp.async.cg.shared.global [%0], [%1], 16;\n"
                 :: "r"(smem_u32(smem_dst)), "l"(gsrc));
}

extern __shared__ char smem_raw[];

#if USE_TC
__device__ __forceinline__ uint32_t elect_one_pred() {
    uint32_t pred;
    asm volatile("{\n\t.reg .pred p;\n\telect.sync _|p, 0xFFFFFFFF;\n\t"
                 "selp.b32 %0, 1, 0, p;\n\t}" : "=r"(pred));
    return pred;
}
__device__ __forceinline__ uint32_t cluster_rank() {
    uint32_t r;
    asm("mov.u32 %0, %%cluster_ctarank;" : "=r"(r));
    return r;
}
static constexpr uint64_t DESC_BASE_SW128 =
    (uint64_t(2) << 61) | (uint64_t(1) << 46) | (uint64_t(64) << 32) | (uint64_t(1) << 16);
__device__ __forceinline__ uint64_t make_desc(uint32_t addr) {
    return DESC_BASE_SW128 | ((uint64_t)(addr >> 4) & 0x3FFF);
}
static constexpr uint32_t MMA_IDESC_N128 = (1u << 4) | (16u << 17) | (8u << 24);
// cg2: f16 x f16 -> f32, M=256 (16<<24), N=256 (32<<17)
static constexpr uint32_t MMA_IDESC_CG2  = (1u << 4) | (32u << 17) | (16u << 24);

__device__ __forceinline__ void mma_f16_ss(uint32_t d_tmem, uint64_t a_desc,
                                           uint64_t b_desc, uint32_t idesc,
                                           uint32_t en) {
    asm volatile(
        "{\n\t.reg .pred p;\n\tsetp.ne.u32 p, %5, 0;\n\t"
        "tcgen05.mma.cta_group::1.kind::f16 [%0], %1, %2, %3, {%4, %4, %4, %4}, p;\n\t}"
        :: "r"(d_tmem), "l"(a_desc), "l"(b_desc), "r"(idesc), "r"(0u), "r"(en)
        : "memory");
}
__device__ __forceinline__ void mma_f16_ss_cg2(uint32_t d_tmem, uint64_t a_desc,
                                               uint64_t b_desc, uint32_t en) {
    asm volatile(
        "{\n\t.reg .pred p;\n\tsetp.ne.u32 p, %5, 0;\n\t"
        "tcgen05.mma.cta_group::2.kind::f16 [%0], %1, %2, %3, "
        "{%4, %4, %4, %4, %4, %4, %4, %4}, p;\n\t}"
        :: "r"(d_tmem), "l"(a_desc), "l"(b_desc), "r"(MMA_IDESC_CG2), "r"(0u), "r"(en)
        : "memory");
}
#define TC_ALLOC(smem_addr, ncols) \
    asm volatile("tcgen05.alloc.cta_group::1.sync.aligned.shared::cta.b32 [%0], %1;" \
                 :: "r"(smem_addr), "r"(ncols) : "memory")
#define TC_DEALLOC(tmem, ncols) \
    asm volatile("tcgen05.dealloc.cta_group::1.sync.aligned.b32 %0, %1;" :: "r"(tmem), "r"(ncols))
#define TC_RELINQ() \
    asm volatile("tcgen05.relinquish_alloc_permit.cta_group::1.sync.aligned;")
#define TC_ALLOC_CG2(smem_addr, ncols) \
    asm volatile("tcgen05.alloc.cta_group::2.sync.aligned.shared::cta.b32 [%0], %1;" \
                 :: "r"(smem_addr), "r"(ncols) : "memory")
#define TC_DEALLOC_CG2(tmem, ncols) \
    asm volatile("tcgen05.dealloc.cta_group::2.sync.aligned.b32 %0, %1;" :: "r"(tmem), "r"(ncols))
#define TC_RELINQ_CG2() \
    asm volatile("tcgen05.relinquish_alloc_permit.cta_group::2.sync.aligned;")
#define TC_COMMIT(mbar) \
    asm volatile("tcgen05.commit.cta_group::1.mbarrier::arrive::one.shared::cluster.b64 [%0];" \
                 :: "r"(mbar) : "memory")
#define TC_COMMIT_MC_CG2(mbar, mask) \
    asm volatile("tcgen05.commit.cta_group::2.mbarrier::arrive::one.shared::cluster.multicast::cluster.b64 [%0], %1;" \
                 :: "r"(mbar), "h"((uint16_t)(mask)) : "memory")
#define TC_FENCE_AFTER()  asm volatile("tcgen05.fence::after_thread_sync;" ::: "memory")
#define TC_WAIT_LD() asm volatile("tcgen05.wait::ld.sync.aligned;" ::: "memory")
#define MBAR_INIT(mbar, cnt) \
    asm volatile("mbarrier.init.shared.b64 [%0], %1;" :: "r"(mbar), "r"(cnt) : "memory")
#define MBAR_EXPECT_TX(mbar, bytes) \
    asm volatile("mbarrier.arrive.expect_tx.shared.b64 _, [%0], %1;" \
                 :: "r"(mbar), "r"(bytes) : "memory")
#define MBAR_ARRIVE(mbar) \
    asm volatile("mbarrier.arrive.shared.b64 _, [%0];" :: "r"(mbar) : "memory")
#define MBAR_ARRIVE_CLUSTER(local_mbar, target_rank) \
    asm volatile( \
        "{\n\t.reg .b32 remAddr;\n\t" \
        "mapa.shared::cluster.u32 remAddr, %0, %1;\n\t" \
        "mbarrier.arrive.shared::cluster.b64 _, [remAddr];\n\t}" \
        :: "r"(local_mbar), "r"(target_rank) : "memory")
#define FENCE_ASYNC_SHARED() asm volatile("fence.proxy.async.shared::cta;" ::: "memory")
#define CLUSTER_SYNC() do { \
    asm volatile("barrier.cluster.arrive.aligned;" ::: "memory"); \
    asm volatile("barrier.cluster.wait.aligned;" ::: "memory"); \
} while (0)

// cg2 TMA: dest local SMEM, complete_tx to LEADER's barrier (bit 24 cleared).
__device__ __forceinline__ void tma_load_3d_cg2(uint32_t smem_addr, const void* tmap,
                                                int cx, int cy, uint32_t mbar) {
    asm volatile(
        "{\n\t.reg .b32 lb;\n\t"
        "and.b32 lb, %4, 0xFEFFFFFF;\n\t"
        "cp.async.bulk.tensor.3d.cta_group::2.shared::cluster.global"
        ".tile.mbarrier::complete_tx::bytes [%0], [%1, {%2, %3, 0}], [lb];\n\t}"
        :: "r"(smem_addr), "l"(tmap), "r"(cx), "r"(cy), "r"(mbar) : "memory");
}

#define LDTM_X32(r, addr) \
    asm volatile( \
        "tcgen05.ld.sync.aligned.32x32b.x32.b32 " \
        "{%0, %1, %2, %3, %4, %5, %6, %7, " \
        " %8, %9, %10, %11, %12, %13, %14, %15, " \
        " %16, %17, %18, %19, %20, %21, %22, %23, " \
        " %24, %25, %26, %27, %28, %29, %30, %31}, [%32];" \
        : "=r"((r)[0]),  "=r"((r)[1]),  "=r"((r)[2]),  "=r"((r)[3]), \
          "=r"((r)[4]),  "=r"((r)[5]),  "=r"((r)[6]),  "=r"((r)[7]), \
          "=r"((r)[8]),  "=r"((r)[9]),  "=r"((r)[10]), "=r"((r)[11]), \
          "=r"((r)[12]), "=r"((r)[13]), "=r"((r)[14]), "=r"((r)[15]), \
          "=r"((r)[16]), "=r"((r)[17]), "=r"((r)[18]), "=r"((r)[19]), \
          "=r"((r)[20]), "=r"((r)[21]), "=r"((r)[22]), "=r"((r)[23]), \
          "=r"((r)[24]), "=r"((r)[25]), "=r"((r)[26]), "=r"((r)[27]), \
          "=r"((r)[28]), "=r"((r)[29]), "=r"((r)[30]), "=r"((r)[31]) \
        : "r"(addr))

__device__ __forceinline__ void mbar_wait_parity(uint32_t mbar, uint32_t parity) {
    asm volatile(
        "{\n\t.reg .pred P1;\n\t"
        "WAIT_LOOP_%=:\n\t"
        "mbarrier.try_wait.parity.acquire.cta.shared::cta.b64 P1, [%0], %1, 0x989680;\n\t"
        "@P1 bra.uni WAIT_DONE_%=;\n\t"
        "bra.uni WAIT_LOOP_%=;\n\t"
        "WAIT_DONE_%=:\n\t}"
        :: "r"(mbar), "r"(parity) : "memory");
}

// Epilogue for a local BM=128 x BN=256 half-tile (round-12 proven mapping).
__device__ __forceinline__ void p_epilogue(
    uint32_t dtmem, int wid, int lane, int m0, int n0,
    const float* cosb, const float* sinb,
    const float* bq, const float* bk, const float* bv, float* out) {
    const int row = ((wid & 3) << 5) + lane;
    const int m = m0 + row;
    const int bt = m >> 12;
    const int s  = m & 4095;
    const int nbase = n0 + (wid >> 2) * 128;
    const int head = nbase >> 7;
    const bool isq = head < NH;
    const bool isk = (head >= NH) && (head < NH + NKV);
    const float* bias;
    size_t obase;
    if (isq)      { bias = bq + nbase;
                    obase = (((size_t)bt * NH + head) * SS + s) * DD; }
    else if (isk) { bias = bk + (nbase - NH * DD);
                    obase = QTOT + (((size_t)bt * NKV + (head - NH)) * SS + s) * DD; }
    else          { bias = bv + (nbase - (NH + NKV) * DD);
                    obase = QTOT + KTOT + (((size_t)bt * NKV + (head - NH - NKV)) * SS + s) * DD; }
    const uint32_t dbase = dtmem + (wid >> 2) * 128;

#pragma unroll
    for (int half = 0; half < 2; half++) {
        uint32_t rlo[32], rhi[32];
        LDTM_X32(rlo, dbase + half * 32);
        LDTM_X32(rhi, dbase + half * 32 + 64);
        TC_WAIT_LD();

        float vlo[32], vhi[32];
#pragma unroll
        for (int i = 0; i < 32; i++) {
            vlo[i] = __uint_as_float(rlo[i]) + bias[half * 32 + i];
            vhi[i] = __uint_as_float(rhi[i]) + bias[half * 32 + 64 + i];
        }
        if (isq || isk) {
            const float* cp = cosb + (size_t)m * DD + half * 32;
            const float* sp = sinb + (size_t)m * DD + half * 32;
#pragma unroll
            for (int i = 0; i < 32; i++) {
                float c = cp[i], sn = sp[i];
                float lo = vlo[i] * c - vhi[i] * sn;
                float hi = vhi[i] * c + vlo[i] * sn;
                vlo[i] = lo; vhi[i] = hi;
            }
        }
        float* o = out + obase + half * 32;
#pragma unroll
        for (int i = 0; i < 8; i++) {
            *reinterpret_cast<float4*>(o + i * 4) =
                make_float4(vlo[i*4], vlo[i*4+1], vlo[i*4+2], vlo[i*4+3]);
            *reinterpret_cast<float4*>(o + 64 + i * 4) =
                make_float4(vhi[i*4], vhi[i*4+1], vhi[i*4+2], vhi[i*4+3]);
        }
    }
}

// Big-tile epilogue for the backup kernel (round-6 proven).
__device__ __forceinline__ void tc_epilogue(
    uint32_t tmem_base, int wid, int lane, int m0, int n0,
    const float* cosb, const float* sinb,
    const float* bq, const float* bk, const float* bv, float* out) {
    const int sub = wid >> 2;
    const int row = ((wid & 3) << 5) + lane;
    const int m = m0 + sub * 128 + row;
    const int bt = m >> 12;
    const int s  = m & 4095;
    const uint32_t dbase = tmem_base + sub * 256;

#pragma unroll
    for (int hc = 0; hc < 2; hc++) {
        const int nbase = n0 + hc * 128;
        const int head = nbase >> 7;
        const bool isq = head < NH;
        const bool isk = (head >= NH) && (head < NH + NKV);
        const float* bias;
        size_t obase;
        if (isq)      { bias = bq + nbase;
                        obase = (((size_t)bt * NH + head) * SS + s) * DD; }
        else if (isk) { bias = bk + (nbase - NH * DD);
                        obase = QTOT + (((size_t)bt * NKV + (head - NH)) * SS + s) * DD; }
        else          { bias = bv + (nbase - (NH + NKV) * DD);
                        obase = QTOT + KTOT + (((size_t)bt * NKV + (head - NH - NKV)) * SS + s) * DD; }

#pragma unroll
        for (int half = 0; half < 2; half++) {
            uint32_t rlo[32], rhi[32];
            LDTM_X32(rlo, dbase + hc * 128 + half * 32);
            LDTM_X32(rhi, dbase + hc * 128 + half * 32 + 64);
            TC_WAIT_LD();

            float vlo[32], vhi[32];
#pragma unroll
            for (int i = 0; i < 32; i++) {
                vlo[i] = __uint_as_float(rlo[i]) + bias[half * 32 + i];
                vhi[i] = __uint_as_float(rhi[i]) + bias[half * 32 + 64 + i];
            }
            if (isq || isk) {
                const float* cp = cosb + (size_t)m * DD + half * 32;
                const float* sp = sinb + (size_t)m * DD + half * 32;
#pragma unroll
                for (int i = 0; i < 32; i++) {
                    float c = cp[i], sn = sp[i];
                    float lo = vlo[i] * c - vhi[i] * sn;
                    float hi = vhi[i] * c + vlo[i] * sn;
                    vlo[i] = lo; vhi[i] = hi;
                }
            }
            float* o = out + obase + half * 32;
#pragma unroll
            for (int i = 0; i < 8; i++) {
                *reinterpret_cast<float4*>(o + i * 4) =
                    make_float4(vlo[i*4], vlo[i*4+1], vlo[i*4+2], vlo[i*4+3]);
                *reinterpret_cast<float4*>(o + 64 + i * 4) =
                    make_float4(vhi[i*4], vhi[i*4+1], vhi[i*4+2], vhi[i*4+3]);
            }
        }
    }
}
#endif  // USE_TC

// ===========================================================================
// PRIMARY: persistent cluster(2,1,1) cta_group::2 tcgen05 kernel.
// EXACT ROUND-14 WINNER (290.3us): 4-stage x 32KB ring, 132KB smem.
// grid (2, 74) = 148 persistent CTAs, pair = blockIdx.y, rank along x.
// Pair tile = M256 x N256. Each CTA holds A-half + B-half (no replication).
// All 4 TMA loads complete_tx on LEADER's FULL bar (expect_tx 64KB).
// Leader (rank 0) issues cg2 MMA; commit.cg2 multicast releases both CTAs.
// TMEM halves 0/256 double-buffered: epilogue(t) overlaps mainloop(t+1).
// Warps 0-7: epilogue. Warp 8 lane0: producer. Warp 9 lane0 (leader): MMA.
// mbars: FULL(s)=+16+s*16 cnt1, EMPTY(s)=+24+s*16 cnt1,
//        MDONE[h]=+80+h*8 cnt1, EDONE[h]=+96+h*8 cnt16 (leader).
// ===========================================================================
__global__ __launch_bounds__(320, 1) __cluster_dims__(2, 1, 1)
void qkv_gemm_tma(const __grid_constant__ TMap tma_a,
                  const __grid_constant__ TMap tma_b,
                  const float* __restrict__ cosb, const float* __restrict__ sinb,
                  const float* __restrict__ bq, const float* __restrict__ bk,
                  const float* __restrict__ bv, float* __restrict__ out) {
#if USE_TC
    const int tid  = threadIdx.x;
    const int wid  = tid >> 5, lane = tid & 31;
    const uint32_t rank = cluster_rank();      // 0/1 along x
    const int pair = blockIdx.y;

    const uint32_t smem_base = smem_u32(smem_raw);
    const uint32_t FULL0 = smem_base + 16, EMPTY0 = smem_base + 24;
    const uint32_t MDONE0 = smem_base + 80, EDONE0 = smem_base + 96;

    if (wid == 0) TC_ALLOC_CG2(smem_base, 512);
    if (tid == 0) {
#pragma unroll
        for (int s = 0; s < P_NSTAGE; s++) {
            MBAR_INIT(FULL0 + s * 16, 1);     // leader: expect_tx arrival
            MBAR_INIT(EMPTY0 + s * 16, 1);    // one cg2 commit-mc arrival
        }
        MBAR_INIT(MDONE0, 1);     MBAR_INIT(MDONE0 + 8, 1);
        MBAR_INIT(EDONE0, 16);    MBAR_INIT(EDONE0 + 8, 16);  // 8 warps x 2 CTAs
    }
    __syncthreads();
    CLUSTER_SYNC();

    uint32_t tmem_base;
    asm volatile("ld.shared.b32 %0, [%1];" : "=r"(tmem_base) : "r"(smem_base));

    if (tid == 256) {
        // ================= TMA producer (both CTAs) =================
        uint32_t pph = 1;
        int slot = 0;
        for (int pt = pair; pt < NPT; pt += NPAIRS) {
            const int m0 = (pt / NTILE_N) * 256 + (int)rank * 128;  // my A half
            const int n0 = (pt % NTILE_N) * 256 + (int)rank * 128;  // my B half
            for (int kt = 0; kt < P_NKT; kt++) {
                mbar_wait_parity(EMPTY0 + slot * 16, pph);
                uint32_t sa = smem_base + P_SMEM_DATA + slot * P_STAGE;
                if (rank == 0)
                    MBAR_EXPECT_TX(FULL0 + slot * 16, 2 * P_STAGE);  // 64KB total
                tma_load_3d_cg2(sa, &tma_a, kt * P_BK, m0, FULL0 + slot * 16);
                tma_load_3d_cg2(sa + P_A_BYTES, &tma_b, kt * P_BK, n0,
                                FULL0 + slot * 16);
                if (++slot == P_NSTAGE) { slot = 0; pph ^= 1; }
            }
        }
    } else if (tid == 288 && rank == 0) {
        // ================= MMA issuer (leader only) =================
        uint32_t cph = 0;
        int slot = 0;
        uint32_t eph[2] = {1, 1};
        int ti = 0;
        for (int pt = pair; pt < NPT; pt += NPAIRS) {
            const int half = ti & 1;
            mbar_wait_parity(EDONE0 + half * 8, eph[half]);  // both epilogues done
            eph[half] ^= 1;
            const uint32_t dt = tmem_base + half * 256;
            for (int kt = 0; kt < P_NKT; kt++) {
                mbar_wait_parity(FULL0 + slot * 16, cph);
                uint32_t sa = smem_base + P_SMEM_DATA + slot * P_STAGE;
                uint64_t ad = make_desc(sa);               // A halves in both CTAs
                uint64_t bd = make_desc(sa + P_A_BYTES);   // B halves in both CTAs
#pragma unroll
                for (int ks = 0; ks < 4; ks++) {
                    uint32_t en = (kt > 0 || ks > 0) ? 1u : 0u;
                    mma_f16_ss_cg2(dt, ad + ks * 2, bd + ks * 2, en);
                }
                TC_COMMIT_MC_CG2(EMPTY0 + slot * 16, 0x3);
                if (++slot == P_NSTAGE) { slot = 0; cph ^= 1; }
            }
            TC_COMMIT_MC_CG2(MDONE0 + half * 8, 0x3);     // tile done, both CTAs
            ti++;
        }
    } else if (wid < 8) {
        // ================= epilogue warps (both CTAs) =================
        uint32_t mph[2] = {0, 0};
        int ti = 0;
        for (int pt = pair; pt < NPT; pt += NPAIRS) {
            const int half = ti & 1;
            const int m0 = (pt / NTILE_N) * 256 + (int)rank * 128;
            const int n0 = (pt % NTILE_N) * 256;
            mbar_wait_parity(MDONE0 + half * 8, mph[half]);
            mph[half] ^= 1;
            TC_FENCE_AFTER();
            p_epilogue(tmem_base + half * 256, wid, lane, m0, n0,
                       cosb, sinb, bq, bk, bv, out);
            if (lane == 0) MBAR_ARRIVE_CLUSTER(EDONE0 + half * 8, 0u);  // leader's bar
            ti++;
        }
    }

    __syncthreads();
    CLUSTER_SYNC();
    if (wid == 0) {
        TC_RELINQ_CG2();
        TC_DEALLOC_CG2(tmem_base, 512);
    }
    CLUSTER_SYNC();
#endif  // USE_TC
}

// ===========================================================================
// cp.async tcgen05 kernel — ROUND-6 PROVEN (423 us) backup. grid (18, 32).
// ===========================================================================
__global__ __launch_bounds__(256, 1)
void qkv_gemm_tc(const float* __restrict__ cosb, const float* __restrict__ sinb,
                 const float* __restrict__ bq, const float* __restrict__ bk,
                 const float* __restrict__ bv, float* __restrict__ out) {
#if USE_TC
    const int tid  = threadIdx.x;
    const int wid  = tid >> 5, lane = tid & 31;
    const int m0 = blockIdx.y * TC_BM;
    const int n0 = blockIdx.x * TC_BN;

    const uint32_t smem_base = smem_u32(smem_raw);
    const uint32_t mbar = smem_base + 8;

    if (wid == 0) TC_ALLOC(smem_base, 512);
    if (tid == 0) MBAR_INIT(mbar, 1);
    __syncthreads();
    uint32_t tmem_base;
    asm volatile("ld.shared.b32 %0, [%1];" : "=r"(tmem_base) : "r"(smem_base));

    const int lc = tid & 7;
    const int lr = tid >> 3;
    auto load_tile = [&](int buf, int kt) {
        char* sb = smem_raw + TC_SMEM_DATA + buf * TC_STAGE_BYTES;
        const __half* Ag = g_A + (size_t)(m0 + lr) * K_ + kt * TC_BK + lc * 8;
#pragma unroll
        for (int i = 0; i < 8; i++) {
            int row = lr + i * 32;
            uint32_t off = row * 128 + ((lc ^ (row & 7)) * 16);
            cp_async16(sb + off, Ag + (size_t)(i * 32) * K_);
        }
        const __half* Bg = g_Wt + (size_t)(n0 + lr) * K_ + kt * TC_BK + lc * 8;
#pragma unroll
        for (int i = 0; i < 8; i++) {
            int row = lr + i * 32;
            uint32_t off = TC_A_BYTES + row * 128 + ((lc ^ (row & 7)) * 16);
            cp_async16(sb + off, Bg + (size_t)(i * 32) * K_);
        }
    };

    load_tile(0, 0);
    asm volatile("cp.async.commit_group;\n");
    load_tile(1, 1);
    asm volatile("cp.async.commit_group;\n");

    uint32_t ph = 0;
    for (int kt = 0; kt < TC_NKT; kt++) {
        if (kt + 1 < TC_NKT) {
            asm volatile("cp.async.wait_group 1;\n");
        } else {
            asm volatile("cp.async.wait_group 0;\n");
        }
        __syncthreads();

        if (wid == 0) {
            FENCE_ASYNC_SHARED();
            if (elect_one_pred()) {
                uint32_t sa = smem_base + TC_SMEM_DATA + (kt % TC_NSTAGE) * TC_STAGE_BYTES;
                uint64_t ad0 = make_desc(sa);
                uint64_t ad1 = make_desc(sa + 16384);
                uint64_t bd0 = make_desc(sa + TC_A_BYTES);
                uint64_t bd1 = make_desc(sa + TC_A_BYTES + 16384);
#pragma unroll
                for (int ks = 0; ks < 4; ks++) {
                    uint32_t en = (kt > 0 || ks > 0) ? 1u : 0u;
                    mma_f16_ss(tmem_base,       ad0 + ks * 2, bd0 + ks * 2, MMA_IDESC_N128, en);
                    mma_f16_ss(tmem_base + 128, ad0 + ks * 2, bd1 + ks * 2, MMA_IDESC_N128, en);
                    mma_f16_ss(tmem_base + 256, ad1 + ks * 2, bd0 + ks * 2, MMA_IDESC_N128, en);
                    mma_f16_ss(tmem_base + 384, ad1 + ks * 2, bd1 + ks * 2, MMA_IDESC_N128, en);
                }
                TC_COMMIT(mbar);
            }
        }
        if (kt >= 1) { mbar_wait_parity(mbar, ph); ph ^= 1; }

        if (kt + 2 < TC_NKT) {
            load_tile((kt + 2) % TC_NSTAGE, kt + 2);
            asm volatile("cp.async.commit_group;\n");
        }
    }
    mbar_wait_parity(mbar, ph);
    TC_FENCE_AFTER();

    tc_epilogue(tmem_base, wid, lane, m0, n0, cosb, sinb, bq, bk, bv, out);

    __syncthreads();
    if (wid == 0) {
        TC_RELINQ();
        TC_DEALLOC(tmem_base, 512);
    }
#endif  // USE_TC
}

// ===========================================================================
// Fallback kernel — ROUND-1 PROVEN CODE, VERBATIM SEMANTICS.
// ===========================================================================
__device__ __forceinline__ void ldsm_x4(uint32_t& r0, uint32_t& r1, uint32_t& r2,
                                        uint32_t& r3, const void* p) {
    uint32_t a = (uint32_t)__cvta_generic_to_shared(p);
    asm volatile("ldmatrix.sync.aligned.m8n8.x4.shared.b16 {%0,%1,%2,%3}, [%4];\n"
                 : "=r"(r0), "=r"(r1), "=r"(r2), "=r"(r3) : "r"(a));
}
__device__ __forceinline__ void mma16816(float* c, const uint32_t* a, const uint32_t* b) {
    asm volatile(
        "mma.sync.aligned.m16n8k16.row.col.f32.f16.f16.f32 "
        "{%0,%1,%2,%3}, {%4,%5,%6,%7}, {%8,%9}, {%0,%1,%2,%3};\n"
        : "+f"(c[0]), "+f"(c[1]), "+f"(c[2]), "+f"(c[3])
        : "r"(a[0]), "r"(a[1]), "r"(a[2]), "r"(a[3]), "r"(b[0]), "r"(b[1]));
}

__global__ __launch_bounds__(256, 2) void qkv_gemm_fb(
    const float* __restrict__ cosb, const float* __restrict__ sinb,
    const float* __restrict__ bq, const float* __restrict__ bk,
    const float* __restrict__ bv, float* __restrict__ out) {

    __half (*As)[FB_BM][FB_BKP] = reinterpret_cast<__half (*)[FB_BM][FB_BKP]>(smem_raw);
    __half (*Bs)[FB_BN][FB_BKP] =
        reinterpret_cast<__half (*)[FB_BN][FB_BKP]>(smem_raw + 2 * FB_BM * FB_BKP * 2);

    const int tid  = threadIdx.x;
    const int warp = tid >> 5, lane = tid & 31;
    const int wm = warp & 3, wn = warp >> 2;
    const int tileN = blockIdx.x;
    const int m0 = blockIdx.y * FB_BM;
    const int n0 = tileN * FB_BN;

    const int lrow = tid >> 2;
    const int lch  = tid & 3;

    float acc[2][8][4];
#pragma unroll
    for (int i = 0; i < 2; i++)
#pragma unroll
        for (int j = 0; j < 8; j++)
#pragma unroll
            for (int l = 0; l < 4; l++) acc[i][j][l] = 0.f;

    auto load_tile = [&](int buf, int kt) {
        const __half* Ag = g_A + (size_t)(m0 + lrow) * K_ + kt * FB_BK + lch * 8;
        cp_async16(&As[buf][lrow][lch * 8], Ag);
        cp_async16(&As[buf][lrow + 64][lch * 8], Ag + (size_t)64 * K_);
        const __half* Bg = g_Wt + (size_t)(n0 + lrow) * K_ + kt * FB_BK + lch * 8;
        cp_async16(&Bs[buf][lrow][lch * 8], Bg);
        cp_async16(&Bs[buf][lrow + 64][lch * 8], Bg + (size_t)64 * K_);
    };

    load_tile(0, 0);
    asm volatile("cp.async.commit_group;\n");

    for (int kt = 0; kt < FB_NKT; kt++) {
        asm volatile("cp.async.wait_group 0;\n");
        __syncthreads();
        if (kt + 1 < FB_NKT) {
            load_tile((kt + 1) & 1, kt + 1);
            asm volatile("cp.async.commit_group;\n");
        }
        const int buf = kt & 1;

#pragma unroll
        for (int ks = 0; ks < 2; ks++) {
            uint32_t a[2][4];
            uint32_t b[8][2];
            const int kc = ks * 16 + (lane >> 4) * 8;
            const int rsel = lane & 15;
#pragma unroll
            for (int fm = 0; fm < 2; fm++)
                ldsm_x4(a[fm][0], a[fm][1], a[fm][2], a[fm][3],
                        &As[buf][wm * 32 + fm * 16 + rsel][kc]);
#pragma unroll
            for (int g = 0; g < 4; g++) {
                uint32_t t0, t1, t2, t3;
                ldsm_x4(t0, t1, t2, t3, &Bs[buf][wn * 64 + g * 16 + rsel][kc]);
                b[g * 2][0] = t0;     b[g * 2][1] = t2;
                b[g * 2 + 1][0] = t1; b[g * 2 + 1][1] = t3;
            }
#pragma unroll
            for (int fm = 0; fm < 2; fm++)
#pragma unroll
                for (int fn = 0; fn < 8; fn++)
                    mma16816(acc[fm][fn], a[fm], b[fn]);
        }
    }

    __syncthreads();
    float (*Cs)[132] = reinterpret_cast<float (*)[132]>(smem_raw);
#pragma unroll
    for (int fm = 0; fm < 2; fm++) {
        int r = wm * 32 + fm * 16 + (lane >> 2);
#pragma unroll
        for (int fn = 0; fn < 8; fn++) {
            int c = wn * 64 + fn * 8 + (lane & 3) * 2;
            Cs[r][c]         = acc[fm][fn][0];
            Cs[r][c + 1]     = acc[fm][fn][1];
            Cs[r + 8][c]     = acc[fm][fn][2];
            Cs[r + 8][c + 1] = acc[fm][fn][3];
        }
    }
    __syncthreads();

    const bool is_q = (tileN < NH);
    const bool is_k = (tileN >= NH) && (tileN < NH + NKV);
    const float* bias;
    if (is_q)       bias = bq + n0;
    else if (is_k)  bias = bk + (n0 - NH * DD);
    else            bias = bv + (n0 - (NH + NKV) * DD);

#pragma unroll 4
    for (int it = 0; it < 16; it++) {
        int r = (tid >> 5) + it * 8;
        int c = (tid & 31) * 4;
        int m = m0 + r;
        int bt = m >> 12;
        int s  = m & 4095;

        float vv[4];
        if (is_q || is_k) {
#pragma unroll
            for (int j = 0; j < 4; j++) {
                int cj = c + j;
                float val = Cs[r][cj] + bias[cj];
                float pr  = Cs[r][cj ^ 64] + bias[cj ^ 64];
                float cse = cosb[(size_t)m * DD + cj];
                float sne = sinb[(size_t)m * DD + cj];
                float rot = (cj < 64) ? -pr : pr;
                vv[j] = val * cse + rot * sne;
            }
        } else {
#pragma unroll
            for (int j = 0; j < 4; j++) vv[j] = Cs[r][c + j] + bias[c + j];
        }

        size_t off;
        if (is_q)
            off = (((size_t)bt * NH + tileN) * SS + s) * DD + c;
        else if (is_k)
            off = QTOT + (((size_t)bt * NKV + (tileN - NH)) * SS + s) * DD + c;
        else
            off = QTOT + KTOT + (((size_t)bt * NKV + (tileN - NH - NKV)) * SS + s) * DD + c;

        *reinterpret_cast<float4*>(out + off) = make_float4(vv[0], vv[1], vv[2], vv[3]);
    }
}

// ---------------------------------------------------------------------------
extern "C" void kernel_launch(void* const* d_in, const int* in_sizes, int n_in,
                              void* d_out, int out_size) {
    const float* hs   = (const float*)d_in[0];
    const float* cosb = (const float*)d_in[1];
    const float* sinb = (const float*)d_in[2];
    const float* Wq   = (const float*)d_in[3];
    const float* bq   = (const float*)d_in[4];
    const float* Wk   = (const float*)d_in[5];
    const float* bk   = (const float*)d_in[6];
    const float* Wv   = (const float*)d_in[7];
    const float* bv   = (const float*)d_in[8];
    float* out = (float*)d_out;

    cudaFuncAttributes pa;
    bool use_tc = false;
    if (cudaFuncGetAttributes(&pa, arch_probe) == cudaSuccess)
        use_tc = (pa.sharedSizeBytes >= 2048);

    int n8 = (M_ * K_) / 8;
    convert_hidden<<<(n8 + 255) / 256, 256>>>(hs, n8);

    dim3 gw(N_ / 32, K_ / 32);
    convert_weights<<<gw, dim3(32, 8)>>>(Wq, Wk, Wv);

    if (use_tc) {
        EncodeFn enc = nullptr;
        {
            void* p = nullptr;
            cudaDriverEntryPointQueryResult st;
            if (cudaGetDriverEntryPoint("cuTensorMapEncodeTiled", &p,
                                        cudaEnableDefault, &st) == cudaSuccess &&
                st == cudaDriverEntryPointSuccess && p)
                enc = (EncodeFn)p;
        }
        if (!enc && &cuTensorMapEncodeTiled != nullptr)
            enc = (EncodeFn)cuTensorMapEncodeTiled;

        bool tma_ok = false;
        TMap ta, tb;
        if (enc) {
            void* pA = nullptr; void* pB = nullptr;
            cudaGetSymbolAddress(&pA, g_A);
            cudaGetSymbolAddress(&pB, g_Wt);
            if (pA && pB) {
                unsigned long long dimsA[3] = { (unsigned long long)K_, (unsigned long long)M_, 1 };
                unsigned long long dimsB[3] = { (unsigned long long)K_, (unsigned long long)N_, 1 };
                unsigned long long strA[2]  = { (unsigned long long)K_ * 2,
                                                (unsigned long long)K_ * 2 * M_ };
                unsigned long long strB[2]  = { (unsigned long long)K_ * 2,
                                                (unsigned long long)K_ * 2 * N_ };
                unsigned boxH[3] = { P_BK, 128, 1 };   // 64-half x 128-row tiles
                unsigned es[3] = { 1, 1, 1 };
                int r1 = enc(&ta, 6, 3, pA, dimsA, strA, boxH, es, 0, 3, 2, 0);
                int r2 = enc(&tb, 6, 3, pB, dimsB, strB, boxH, es, 0, 3, 2, 0);
                tma_ok = (r1 == 0 && r2 == 0);
            }
        }
        if (tma_ok) {
            cudaFuncSetAttribute(qkv_gemm_tma, cudaFuncAttributeMaxDynamicSharedMemorySize,
                                 P_SMEM_BYTES);
            dim3 gg(2, NPAIRS);                // 148 persistent CTAs, cluster (2,1,1)
            qkv_gemm_tma<<<gg, 320, P_SMEM_BYTES>>>(ta, tb, cosb, sinb, bq, bk, bv, out);
        } else {
            cudaFuncSetAttribute(qkv_gemm_tc, cudaFuncAttributeMaxDynamicSharedMemorySize,
                                 TC_SMEM_BYTES);
            dim3 gg(N_ / TC_BN, M_ / TC_BM);
            qkv_gemm_tc<<<gg, 256, TC_SMEM_BYTES>>>(cosb, sinb, bq, bk, bv, out);
        }
    } else {
        cudaFuncSetAttribute(qkv_gemm_fb, cudaFuncAttributeMaxDynamicSharedMemorySize,
                             FB_SMEM_BYTES);
        dim3 gg(N_ / FB_BN, M_ / FB_BM);
        qkv_gemm_fb<<<gg, 256, FB_SMEM_BYTES>>>(cosb, sinb, bq, bk, bv, out);
    }
}